// round 1
// baseline (speedup 1.0000x reference)
#include <cuda_runtime.h>
#include <math.h>

#define BATCH 8
#define CH    512
#define NSP   4096      // H*W
#define NG    32
#define CPG   16        // CH/NG
#define SCALE 0.044194173824159216f   // 1/sqrt(512)

// ---------------- scratch (device globals: allocation-free) ----------------
__device__ float g_h   [(size_t)BATCH * CH * NSP];          //  64 MB
__device__ float g_qkv [(size_t)BATCH * 3 * CH * NSP];      // 192 MB
__device__ float g_attn[(size_t)BATCH * NSP * NSP];         // 512 MB
__device__ float g_out2[(size_t)BATCH * CH * NSP];          //  64 MB

// ---------------- GroupNorm: one block per (b, group) ----------------
__global__ void gn_kernel(const float* __restrict__ x,
                          const float* __restrict__ gamma,
                          const float* __restrict__ beta) {
    const int b = blockIdx.x >> 5;
    const int g = blockIdx.x & 31;
    const size_t base = ((size_t)b * CH + (size_t)g * CPG) * NSP;
    const float4* x4 = (const float4*)(x + base);
    float4* h4 = (float4*)(g_h + base);
    const int tid = threadIdx.x;
    const int NV = CPG * NSP / 4;   // 16384 float4

    float s = 0.f, ss = 0.f;
    for (int i = tid; i < NV; i += 256) {
        float4 v = x4[i];
        s  += v.x + v.y + v.z + v.w;
        ss += v.x * v.x + v.y * v.y + v.z * v.z + v.w * v.w;
    }
    __shared__ float rs[256], rq[256];
    rs[tid] = s; rq[tid] = ss;
    __syncthreads();
    for (int o = 128; o > 0; o >>= 1) {
        if (tid < o) { rs[tid] += rs[tid + o]; rq[tid] += rq[tid + o]; }
        __syncthreads();
    }
    const float inv_n = 1.f / (float)(CPG * NSP);
    const float mean  = rs[0] * inv_n;
    const float var   = rq[0] * inv_n - mean * mean;
    const float rstd  = rsqrtf(var + 1e-5f);

    for (int i = tid; i < NV; i += 256) {
        const int c = g * CPG + (i >> 10);    // (i*4)/4096
        const float ga = gamma[c] * rstd;
        const float be = beta[c] - mean * ga;
        float4 v = x4[i];
        v.x = v.x * ga + be; v.y = v.y * ga + be;
        v.z = v.z * ga + be; v.w = v.w * ga + be;
        h4[i] = v;
    }
}

// ---------------- generic NN GEMM body: C[m,n] = sum_k A[m,k]*B[k,n] ----------------
// A row-major [M, CH] (k contiguous); B [CH, NSP] (n contiguous).
// 64x64 tile, BK=16, 256 threads, 4x4 per thread.
template <bool RESID>
__device__ __forceinline__ void gemm_nn_body(
    const float* __restrict__ A, const float* __restrict__ Bp,
    const float* __restrict__ bias, const float* __restrict__ resid,
    float* __restrict__ out) {
    __shared__ float As[64][16];   // m-major (A reads are broadcast)
    __shared__ float Bs[16][64];   // k-major

    const int tid = threadIdx.x;
    const int tr = tid >> 4, tc = tid & 15;
    const int m0 = blockIdx.y * 64, n0 = blockIdx.x * 64;
    const int a_row = tid >> 2, a_k = (tid & 3) << 2;
    const int b_k   = tid >> 4, b_n = (tid & 15) << 2;

    float acc[4][4] = {};

    for (int k0 = 0; k0 < CH; k0 += 16) {
        *(float4*)&As[a_row][a_k] =
            *(const float4*)(A + (size_t)(m0 + a_row) * CH + k0 + a_k);
        *(float4*)&Bs[b_k][b_n] =
            *(const float4*)(Bp + (size_t)(k0 + b_k) * NSP + n0 + b_n);
        __syncthreads();
#pragma unroll
        for (int kk = 0; kk < 16; kk++) {
            float a[4];
#pragma unroll
            for (int i = 0; i < 4; i++) a[i] = As[tr * 4 + i][kk];
            float4 bq = *(const float4*)&Bs[kk][tc * 4];
            const float bb[4] = {bq.x, bq.y, bq.z, bq.w};
#pragma unroll
            for (int i = 0; i < 4; i++)
#pragma unroll
                for (int j = 0; j < 4; j++) acc[i][j] += a[i] * bb[j];
        }
        __syncthreads();
    }
#pragma unroll
    for (int i = 0; i < 4; i++) {
        const int m = m0 + tr * 4 + i;
        const float bi = bias[m];
        const size_t off = (size_t)m * NSP + n0 + tc * 4;
        float4 r = make_float4(acc[i][0] + bi, acc[i][1] + bi,
                               acc[i][2] + bi, acc[i][3] + bi);
        if (RESID) {
            float4 xv = *(const float4*)(resid + off);
            r.x += xv.x; r.y += xv.y; r.z += xv.z; r.w += xv.w;
        }
        *(float4*)(out + off) = r;
    }
}

__global__ void gemm_qkv_kernel(const float* __restrict__ W,
                                const float* __restrict__ bias) {
    const int b = blockIdx.z;
    gemm_nn_body<false>(W, g_h + (size_t)b * CH * NSP, bias, nullptr,
                        g_qkv + (size_t)b * 3 * CH * NSP);
}

__global__ void gemm_out_kernel(const float* __restrict__ W,
                                const float* __restrict__ bias,
                                const float* __restrict__ x,
                                float* __restrict__ y) {
    const int b = blockIdx.z;
    gemm_nn_body<true>(W, g_out2 + (size_t)b * CH * NSP, bias,
                       x + (size_t)b * CH * NSP, y + (size_t)b * CH * NSP);
}

// ---------------- S = scale * Q^T K  (both operands k-major in gmem) ----------------
__global__ void gemm_s_kernel() {
    const int b = blockIdx.z;
    const int i0 = blockIdx.y * 64, j0 = blockIdx.x * 64;
    const float* Q  = g_qkv + (size_t)b * 3 * CH * NSP;
    const float* Kp = Q + (size_t)CH * NSP;

    __shared__ float As[16][64], Bs[16][64];
    const int tid = threadIdx.x;
    const int tr = tid >> 4, tc = tid & 15;
    const int l_k = tid >> 4, l_s = (tid & 15) << 2;

    float acc[4][4] = {};
    for (int k0 = 0; k0 < CH; k0 += 16) {
        *(float4*)&As[l_k][l_s] =
            *(const float4*)(Q + (size_t)(k0 + l_k) * NSP + i0 + l_s);
        *(float4*)&Bs[l_k][l_s] =
            *(const float4*)(Kp + (size_t)(k0 + l_k) * NSP + j0 + l_s);
        __syncthreads();
#pragma unroll
        for (int kk = 0; kk < 16; kk++) {
            float4 aq = *(const float4*)&As[kk][tr * 4];
            float4 bq = *(const float4*)&Bs[kk][tc * 4];
            const float a[4]  = {aq.x, aq.y, aq.z, aq.w};
            const float bb[4] = {bq.x, bq.y, bq.z, bq.w};
#pragma unroll
            for (int i = 0; i < 4; i++)
#pragma unroll
                for (int j = 0; j < 4; j++) acc[i][j] += a[i] * bb[j];
        }
        __syncthreads();
    }
    float* Sp = g_attn + (size_t)b * NSP * NSP;
#pragma unroll
    for (int i = 0; i < 4; i++) {
        const size_t off = (size_t)(i0 + tr * 4 + i) * NSP + j0 + tc * 4;
        *(float4*)(Sp + off) = make_float4(acc[i][0] * SCALE, acc[i][1] * SCALE,
                                           acc[i][2] * SCALE, acc[i][3] * SCALE);
    }
}

// ---------------- softmax over rows of S (one block per row) ----------------
__global__ void softmax_kernel() {
    float4* p = (float4*)(g_attn +
        ((size_t)blockIdx.y * NSP + blockIdx.x) * NSP);
    const int tid = threadIdx.x;
    float4 v[4];
    float mx = -1e30f;
#pragma unroll
    for (int u = 0; u < 4; u++) {
        v[u] = p[tid + u * 256];
        mx = fmaxf(mx, fmaxf(fmaxf(v[u].x, v[u].y), fmaxf(v[u].z, v[u].w)));
    }
    __shared__ float red[256];
    red[tid] = mx;
    __syncthreads();
    for (int o = 128; o > 0; o >>= 1) {
        if (tid < o) red[tid] = fmaxf(red[tid], red[tid + o]);
        __syncthreads();
    }
    mx = red[0];
    __syncthreads();

    float s = 0.f;
#pragma unroll
    for (int u = 0; u < 4; u++) {
        v[u].x = __expf(v[u].x - mx); v[u].y = __expf(v[u].y - mx);
        v[u].z = __expf(v[u].z - mx); v[u].w = __expf(v[u].w - mx);
        s += v[u].x + v[u].y + v[u].z + v[u].w;
    }
    red[tid] = s;
    __syncthreads();
    for (int o = 128; o > 0; o >>= 1) {
        if (tid < o) red[tid] += red[tid + o];
        __syncthreads();
    }
    const float inv = 1.f / red[0];
#pragma unroll
    for (int u = 0; u < 4; u++) {
        v[u].x *= inv; v[u].y *= inv; v[u].z *= inv; v[u].w *= inv;
        p[tid + u * 256] = v[u];
    }
}

// ---------------- out2[c,i] = sum_j V[c,j] * P[i,j]  (NT GEMM, K=4096) ----------------
__global__ void gemm_av_kernel() {
    const int b = blockIdx.z;
    const int c0 = blockIdx.y * 64, i0 = blockIdx.x * 64;
    const float* V = g_qkv + ((size_t)b * 3 + 2) * CH * NSP;
    const float* P = g_attn + (size_t)b * NSP * NSP;

    __shared__ float As[64][16];   // As[c][j]
    __shared__ float Bs[64][17];   // Bs[i][j], padded to dodge conflicts

    const int tid = threadIdx.x;
    const int tr = tid >> 4, tc = tid & 15;
    const int l_row = tid >> 2, l_k = (tid & 3) << 2;

    float acc[4][4] = {};
    for (int k0 = 0; k0 < NSP; k0 += 16) {
        *(float4*)&As[l_row][l_k] =
            *(const float4*)(V + (size_t)(c0 + l_row) * NSP + k0 + l_k);
        float4 bv = *(const float4*)(P + (size_t)(i0 + l_row) * NSP + k0 + l_k);
        Bs[l_row][l_k + 0] = bv.x; Bs[l_row][l_k + 1] = bv.y;
        Bs[l_row][l_k + 2] = bv.z; Bs[l_row][l_k + 3] = bv.w;
        __syncthreads();
#pragma unroll
        for (int kk = 0; kk < 16; kk++) {
            float a[4], bb[4];
#pragma unroll
            for (int i = 0; i < 4; i++) a[i] = As[tr * 4 + i][kk];
#pragma unroll
            for (int j = 0; j < 4; j++) bb[j] = Bs[tc * 4 + j][kk];
#pragma unroll
            for (int i = 0; i < 4; i++)
#pragma unroll
                for (int j = 0; j < 4; j++) acc[i][j] += a[i] * bb[j];
        }
        __syncthreads();
    }
#pragma unroll
    for (int i = 0; i < 4; i++) {
        const size_t off =
            ((size_t)b * CH + c0 + tr * 4 + i) * NSP + i0 + tc * 4;
        *(float4*)(g_out2 + off - (size_t)b * CH * NSP + (size_t)b * CH * NSP) =
            make_float4(acc[i][0], acc[i][1], acc[i][2], acc[i][3]);
    }
}

// ---------------- launch ----------------
extern "C" void kernel_launch(void* const* d_in, const int* in_sizes, int n_in,
                              void* d_out, int out_size) {
    const float* x     = (const float*)d_in[0];
    const float* gamma = (const float*)d_in[1];
    const float* beta  = (const float*)d_in[2];
    const float* w_qkv = (const float*)d_in[3];
    const float* b_qkv = (const float*)d_in[4];
    const float* w_out = (const float*)d_in[5];
    const float* b_out = (const float*)d_in[6];
    float* y = (float*)d_out;

    gn_kernel<<<BATCH * NG, 256>>>(x, gamma, beta);
    gemm_qkv_kernel<<<dim3(NSP / 64, 3 * CH / 64, BATCH), 256>>>(w_qkv, b_qkv);
    gemm_s_kernel<<<dim3(NSP / 64, NSP / 64, BATCH), 256>>>();
    softmax_kernel<<<dim3(NSP, BATCH), 256>>>();
    gemm_av_kernel<<<dim3(NSP / 64, CH / 64, BATCH), 256>>>();
    gemm_out_kernel<<<dim3(NSP / 64, CH / 64, BATCH), 256>>>(w_out, b_out, x, y);
}

// round 2
// speedup vs baseline: 2.6460x; 2.6460x over previous
#include <cuda_runtime.h>
#include <math.h>
#include <stdint.h>

#define BATCH 8
#define CH    512
#define NSP   4096      // H*W
#define NG    32
#define CPG   16        // CH/NG
#define SCALE 0.044194173824159216f   // 1/sqrt(512)

#define LDSM 132        // smem row stride (floats), float4-aligned, low-conflict

// ---------------- scratch (device globals: allocation-free) ----------------
__device__ float g_h   [(size_t)BATCH * CH * NSP];          //  64 MB
__device__ float g_qkv [(size_t)BATCH * 3 * CH * NSP];      // 192 MB
__device__ float g_attn[(size_t)BATCH * NSP * NSP];         // 512 MB
__device__ float g_out2[(size_t)BATCH * CH * NSP];          //  64 MB

// ---------------- tf32 helpers ----------------
__device__ __forceinline__ float f2tf32(float x) {
    uint32_t u;
    asm("cvt.rna.tf32.f32 %0, %1;" : "=r"(u) : "f"(x));
    return __uint_as_float(u);
}
__device__ __forceinline__ float4 cvt4(float4 v) {
    v.x = f2tf32(v.x); v.y = f2tf32(v.y);
    v.z = f2tf32(v.z); v.w = f2tf32(v.w);
    return v;
}
__device__ __forceinline__ void mma_tf32(float* d, const uint32_t* a, const uint32_t* b) {
    asm volatile(
        "mma.sync.aligned.m16n8k8.row.col.f32.tf32.tf32.f32 "
        "{%0,%1,%2,%3}, {%4,%5,%6,%7}, {%8,%9}, {%0,%1,%2,%3};\n"
        : "+f"(d[0]), "+f"(d[1]), "+f"(d[2]), "+f"(d[3])
        : "r"(a[0]), "r"(a[1]), "r"(a[2]), "r"(a[3]), "r"(b[0]), "r"(b[1]));
}

// ---------------- smem staging ----------------
// Direct: S[k][m] <- g[k][m], g has 32 k-rows of >=128 contiguous floats, row stride ld.
__device__ __forceinline__ void stage_direct(float (*S)[LDSM], const float* __restrict__ g,
                                             size_t ld) {
    const int row = threadIdx.x >> 5;          // 0..7
    const int c4  = (threadIdx.x & 31) << 2;   // 0..124
#pragma unroll
    for (int p = 0; p < 4; p++) {
        float4 v = *(const float4*)(g + (size_t)(row + p * 8) * ld + c4);
        *(float4*)&S[row + p * 8][c4] = cvt4(v);
    }
}
// Transpose: S[k][m] <- g[m][k], g has 128 m-rows with k contiguous, row stride ld.
__device__ __forceinline__ void stage_trans(float (*S)[LDSM], const float* __restrict__ g,
                                            size_t ld) {
    const int m  = threadIdx.x >> 2;           // 0..63
    const int kq = (threadIdx.x & 3) << 2;     // 0,4,8,12
#pragma unroll
    for (int mp = 0; mp < 2; mp++)
#pragma unroll
        for (int kp = 0; kp < 2; kp++) {
            float4 v = *(const float4*)(g + (size_t)(m + mp * 64) * ld + kq + kp * 16);
            const int k = kq + kp * 16, mm = m + mp * 64;
            S[k + 0][mm] = f2tf32(v.x);
            S[k + 1][mm] = f2tf32(v.y);
            S[k + 2][mm] = f2tf32(v.z);
            S[k + 3][mm] = f2tf32(v.w);
        }
}

// ---------------- core 128x128x32 tensor-core step ----------------
__device__ __forceinline__ void mma_compute(const float (*As)[LDSM], const float (*Bs)[LDSM],
                                            float acc[4][4][4], int wm, int wn,
                                            int gid, int tig) {
#pragma unroll
    for (int kk = 0; kk < 4; kk++) {
        uint32_t a[4][4];
#pragma unroll
        for (int i = 0; i < 4; i++) {
            const float* base = &As[kk * 8 + tig][wm * 64 + i * 16 + gid];
            a[i][0] = __float_as_uint(base[0]);
            a[i][1] = __float_as_uint(base[8]);
            a[i][2] = __float_as_uint(base[4 * LDSM]);
            a[i][3] = __float_as_uint(base[4 * LDSM + 8]);
        }
        uint32_t b[4][2];
#pragma unroll
        for (int j = 0; j < 4; j++) {
            const float* bb = &Bs[kk * 8 + tig][wn * 32 + j * 8 + gid];
            b[j][0] = __float_as_uint(bb[0]);
            b[j][1] = __float_as_uint(bb[4 * LDSM]);
        }
#pragma unroll
        for (int i = 0; i < 4; i++)
#pragma unroll
            for (int j = 0; j < 4; j++) mma_tf32(acc[i][j], a[i], b[j]);
    }
}

// ---------------- GroupNorm ----------------
__global__ void gn_kernel(const float* __restrict__ x,
                          const float* __restrict__ gamma,
                          const float* __restrict__ beta) {
    const int b = blockIdx.x >> 5;
    const int g = blockIdx.x & 31;
    const size_t base = ((size_t)b * CH + (size_t)g * CPG) * NSP;
    const float4* x4 = (const float4*)(x + base);
    float4* h4 = (float4*)(g_h + base);
    const int tid = threadIdx.x;
    const int NV = CPG * NSP / 4;

    float s = 0.f, ss = 0.f;
    for (int i = tid; i < NV; i += 256) {
        float4 v = x4[i];
        s  += v.x + v.y + v.z + v.w;
        ss += v.x * v.x + v.y * v.y + v.z * v.z + v.w * v.w;
    }
    __shared__ float rs[256], rq[256];
    rs[tid] = s; rq[tid] = ss;
    __syncthreads();
    for (int o = 128; o > 0; o >>= 1) {
        if (tid < o) { rs[tid] += rs[tid + o]; rq[tid] += rq[tid + o]; }
        __syncthreads();
    }
    const float inv_n = 1.f / (float)(CPG * NSP);
    const float mean  = rs[0] * inv_n;
    const float var   = rq[0] * inv_n - mean * mean;
    const float rstd  = rsqrtf(var + 1e-5f);

    for (int i = tid; i < NV; i += 256) {
        const int c = g * CPG + (i >> 10);
        const float ga = gamma[c] * rstd;
        const float be = beta[c] - mean * ga;
        float4 v = x4[i];
        v.x = v.x * ga + be; v.y = v.y * ga + be;
        v.z = v.z * ga + be; v.w = v.w * ga + be;
        h4[i] = v;
    }
}

// ---------------- QKV: C[o,n] = W[o,:] @ h[:,n] + bias ----------------
__global__ __launch_bounds__(256, 2) void qkv_mma_kernel(const float* __restrict__ W,
                                                         const float* __restrict__ bias) {
    const int b = blockIdx.z;
    const int m0 = blockIdx.y * 128, n0 = blockIdx.x * 128;
    const float* h = g_h + (size_t)b * CH * NSP;
    __shared__ float As[32][LDSM], Bs[32][LDSM];
    float acc[4][4][4] = {};
    const int lane = threadIdx.x & 31, wid = threadIdx.x >> 5;
    const int wm = wid >> 2, wn = wid & 3, gid = lane >> 2, tig = lane & 3;

    for (int k0 = 0; k0 < CH; k0 += 32) {
        stage_trans(As, W + (size_t)m0 * CH + k0, CH);
        stage_direct(Bs, h + (size_t)k0 * NSP + n0, NSP);
        __syncthreads();
        mma_compute(As, Bs, acc, wm, wn, gid, tig);
        __syncthreads();
    }
    float* out = g_qkv + (size_t)b * 3 * CH * NSP;
#pragma unroll
    for (int i = 0; i < 4; i++) {
        const int m = m0 + wm * 64 + i * 16 + gid;
        const float b0 = bias[m], b1 = bias[m + 8];
#pragma unroll
        for (int j = 0; j < 4; j++) {
            const int n = n0 + wn * 32 + j * 8 + 2 * tig;
            *(float2*)(out + (size_t)m * NSP + n) =
                make_float2(acc[i][j][0] + b0, acc[i][j][1] + b0);
            *(float2*)(out + (size_t)(m + 8) * NSP + n) =
                make_float2(acc[i][j][2] + b1, acc[i][j][3] + b1);
        }
    }
}

// ---------------- S = scale * Q^T K ----------------
__global__ __launch_bounds__(256, 2) void s_mma_kernel() {
    const int b = blockIdx.z;
    const int i0 = blockIdx.y * 128, j0 = blockIdx.x * 128;
    const float* Q  = g_qkv + (size_t)b * 3 * CH * NSP;
    const float* Kp = Q + (size_t)CH * NSP;
    __shared__ float As[32][LDSM], Bs[32][LDSM];
    float acc[4][4][4] = {};
    const int lane = threadIdx.x & 31, wid = threadIdx.x >> 5;
    const int wm = wid >> 2, wn = wid & 3, gid = lane >> 2, tig = lane & 3;

    for (int k0 = 0; k0 < CH; k0 += 32) {
        stage_direct(As, Q  + (size_t)k0 * NSP + i0, NSP);
        stage_direct(Bs, Kp + (size_t)k0 * NSP + j0, NSP);
        __syncthreads();
        mma_compute(As, Bs, acc, wm, wn, gid, tig);
        __syncthreads();
    }
    float* Sp = g_attn + (size_t)b * NSP * NSP;
#pragma unroll
    for (int i = 0; i < 4; i++) {
        const int m = i0 + wm * 64 + i * 16 + gid;
#pragma unroll
        for (int j = 0; j < 4; j++) {
            const int n = j0 + wn * 32 + j * 8 + 2 * tig;
            *(float2*)(Sp + (size_t)m * NSP + n) =
                make_float2(acc[i][j][0] * SCALE, acc[i][j][1] * SCALE);
            *(float2*)(Sp + (size_t)(m + 8) * NSP + n) =
                make_float2(acc[i][j][2] * SCALE, acc[i][j][3] * SCALE);
        }
    }
}

// ---------------- softmax over rows of S ----------------
__global__ void softmax_kernel() {
    float4* p = (float4*)(g_attn + ((size_t)blockIdx.y * NSP + blockIdx.x) * NSP);
    const int tid = threadIdx.x;
    float4 v[4];
    float mx = -1e30f;
#pragma unroll
    for (int u = 0; u < 4; u++) {
        v[u] = p[tid + u * 256];
        mx = fmaxf(mx, fmaxf(fmaxf(v[u].x, v[u].y), fmaxf(v[u].z, v[u].w)));
    }
    __shared__ float red[256];
    red[tid] = mx;
    __syncthreads();
    for (int o = 128; o > 0; o >>= 1) {
        if (tid < o) red[tid] = fmaxf(red[tid], red[tid + o]);
        __syncthreads();
    }
    mx = red[0];
    __syncthreads();

    float s = 0.f;
#pragma unroll
    for (int u = 0; u < 4; u++) {
        v[u].x = __expf(v[u].x - mx); v[u].y = __expf(v[u].y - mx);
        v[u].z = __expf(v[u].z - mx); v[u].w = __expf(v[u].w - mx);
        s += v[u].x + v[u].y + v[u].z + v[u].w;
    }
    red[tid] = s;
    __syncthreads();
    for (int o = 128; o > 0; o >>= 1) {
        if (tid < o) red[tid] += red[tid + o];
        __syncthreads();
    }
    const float inv = 1.f / red[0];
#pragma unroll
    for (int u = 0; u < 4; u++) {
        v[u].x *= inv; v[u].y *= inv; v[u].z *= inv; v[u].w *= inv;
        p[tid + u * 256] = v[u];
    }
}

// ---------------- out2[c,i] = sum_j V[c,j] * P[i,j] ----------------
__global__ __launch_bounds__(256, 2) void av_mma_kernel() {
    const int b = blockIdx.z;
    const int m0 = blockIdx.y * 128, n0 = blockIdx.x * 128;   // m=c, n=i
    const float* V = g_qkv + ((size_t)b * 3 + 2) * CH * NSP;
    const float* P = g_attn + (size_t)b * NSP * NSP;
    __shared__ float As[32][LDSM], Bs[32][LDSM];
    float acc[4][4][4] = {};
    const int lane = threadIdx.x & 31, wid = threadIdx.x >> 5;
    const int wm = wid >> 2, wn = wid & 3, gid = lane >> 2, tig = lane & 3;

    for (int k0 = 0; k0 < NSP; k0 += 32) {
        stage_trans(As, V + (size_t)m0 * NSP + k0, NSP);
        stage_trans(Bs, P + (size_t)n0 * NSP + k0, NSP);
        __syncthreads();
        mma_compute(As, Bs, acc, wm, wn, gid, tig);
        __syncthreads();
    }
#pragma unroll
    for (int i = 0; i < 4; i++) {
        const int m = m0 + wm * 64 + i * 16 + gid;
#pragma unroll
        for (int j = 0; j < 4; j++) {
            const int n = n0 + wn * 32 + j * 8 + 2 * tig;
            *(float2*)(g_out2 + ((size_t)b * CH + m) * NSP + n) =
                make_float2(acc[i][j][0], acc[i][j][1]);
            *(float2*)(g_out2 + ((size_t)b * CH + m + 8) * NSP + n) =
                make_float2(acc[i][j][2], acc[i][j][3]);
        }
    }
}

// ---------------- out: y = x + W_out @ out2 + b_out ----------------
__global__ __launch_bounds__(256, 2) void out_mma_kernel(const float* __restrict__ W,
                                                         const float* __restrict__ bias,
                                                         const float* __restrict__ x,
                                                         float* __restrict__ y) {
    const int b = blockIdx.z;
    const int m0 = blockIdx.y * 128, n0 = blockIdx.x * 128;
    const float* hin = g_out2 + (size_t)b * CH * NSP;
    __shared__ float As[32][LDSM], Bs[32][LDSM];
    float acc[4][4][4] = {};
    const int lane = threadIdx.x & 31, wid = threadIdx.x >> 5;
    const int wm = wid >> 2, wn = wid & 3, gid = lane >> 2, tig = lane & 3;

    for (int k0 = 0; k0 < CH; k0 += 32) {
        stage_trans(As, W + (size_t)m0 * CH + k0, CH);
        stage_direct(Bs, hin + (size_t)k0 * NSP + n0, NSP);
        __syncthreads();
        mma_compute(As, Bs, acc, wm, wn, gid, tig);
        __syncthreads();
    }
#pragma unroll
    for (int i = 0; i < 4; i++) {
        const int m = m0 + wm * 64 + i * 16 + gid;
        const float b0 = bias[m], b1 = bias[m + 8];
#pragma unroll
        for (int j = 0; j < 4; j++) {
            const int n = n0 + wn * 32 + j * 8 + 2 * tig;
            const size_t o0 = ((size_t)b * CH + m) * NSP + n;
            const size_t o1 = ((size_t)b * CH + m + 8) * NSP + n;
            float2 x0 = *(const float2*)(x + o0);
            float2 x1 = *(const float2*)(x + o1);
            *(float2*)(y + o0) =
                make_float2(acc[i][j][0] + b0 + x0.x, acc[i][j][1] + b0 + x0.y);
            *(float2*)(y + o1) =
                make_float2(acc[i][j][2] + b1 + x1.x, acc[i][j][3] + b1 + x1.y);
        }
    }
}

// ---------------- launch ----------------
extern "C" void kernel_launch(void* const* d_in, const int* in_sizes, int n_in,
                              void* d_out, int out_size) {
    const float* x     = (const float*)d_in[0];
    const float* gamma = (const float*)d_in[1];
    const float* beta  = (const float*)d_in[2];
    const float* w_qkv = (const float*)d_in[3];
    const float* b_qkv = (const float*)d_in[4];
    const float* w_out = (const float*)d_in[5];
    const float* b_out = (const float*)d_in[6];
    float* y = (float*)d_out;

    gn_kernel<<<BATCH * NG, 256>>>(x, gamma, beta);
    qkv_mma_kernel<<<dim3(NSP / 128, 3 * CH / 128, BATCH), 256>>>(w_qkv, b_qkv);
    s_mma_kernel<<<dim3(NSP / 128, NSP / 128, BATCH), 256>>>();
    softmax_kernel<<<dim3(NSP, BATCH), 256>>>();
    av_mma_kernel<<<dim3(NSP / 128, CH / 128, BATCH), 256>>>();
    out_mma_kernel<<<dim3(NSP / 128, CH / 128, BATCH), 256>>>(w_out, b_out, x, y);
}

// round 3
// speedup vs baseline: 6.7724x; 2.5595x over previous
#include <cuda_runtime.h>
#include <cuda_bf16.h>
#include <math.h>
#include <stdint.h>

#define BATCH 8
#define CH    512
#define NSP   4096
#define NG    32
#define CPG   16
#define SCALE 0.044194173824159216f   // 1/sqrt(512)

// ---------------- scratch (device globals) ----------------
__device__ __nv_bfloat16 g_hb   [(size_t)BATCH * CH * NSP];       //  32 MB
__device__ __nv_bfloat16 g_qkvb [(size_t)BATCH * 3 * CH * NSP];   //  96 MB
__device__ float         g_attn [(size_t)BATCH * NSP * NSP];      // 512 MB
__device__ __nv_bfloat16 g_pb   [(size_t)BATCH * NSP * NSP];      // 256 MB
__device__ __nv_bfloat16 g_out2b[(size_t)BATCH * CH * NSP];       //  32 MB
__device__ __nv_bfloat16 g_wqkvb[(size_t)3 * CH * CH];
__device__ __nv_bfloat16 g_woutb[(size_t)CH * CH];

// ---------------- small helpers ----------------
__device__ __forceinline__ uint32_t pack_bf16(float x, float y) {
    __nv_bfloat162 h = __floats2bfloat162_rn(x, y);
    return *reinterpret_cast<uint32_t*>(&h);
}
__device__ __forceinline__ void cp16(void* s, const void* g) {
    uint32_t sa = (uint32_t)__cvta_generic_to_shared(s);
    asm volatile("cp.async.cg.shared.global [%0], [%1], 16;\n" :: "r"(sa), "l"(g));
}
#define CP_COMMIT()  asm volatile("cp.async.commit_group;\n")
#define CP_WAIT1()   asm volatile("cp.async.wait_group 1;\n")

__device__ __forceinline__ void mma_bf16(float* d, const uint32_t* a, const uint32_t* b) {
    asm volatile(
        "mma.sync.aligned.m16n8k16.row.col.f32.bf16.bf16.f32 "
        "{%0,%1,%2,%3}, {%4,%5,%6,%7}, {%8,%9}, {%0,%1,%2,%3};\n"
        : "+f"(d[0]), "+f"(d[1]), "+f"(d[2]), "+f"(d[3])
        : "r"(a[0]), "r"(a[1]), "r"(a[2]), "r"(a[3]), "r"(b[0]), "r"(b[1]));
}

// ---------------- smem staging (always layout-preserving copies) ----------------
// rowk: S[128][40] halves <- 128 gmem rows (stride ld elems) x 32 halves
__device__ __forceinline__ void stage_rowk(__nv_bfloat16 (*S)[40],
                                           const __nv_bfloat16* g, size_t ld) {
    const int t = threadIdx.x;
    const int seg = t & 3, r0 = t >> 2;
#pragma unroll
    for (int p = 0; p < 2; p++) {
        const int r = r0 + p * 64;
        cp16(&S[r][seg * 8], g + (size_t)r * ld + seg * 8);
    }
}
// krow: S[32][136] halves <- 32 gmem rows (stride ld elems) x 128 halves
__device__ __forceinline__ void stage_krow(__nv_bfloat16 (*S)[136],
                                           const __nv_bfloat16* g, size_t ld) {
    const int t = threadIdx.x;
    const int seg = t & 15, r0 = t >> 4;
#pragma unroll
    for (int p = 0; p < 2; p++) {
        const int r = r0 + p * 16;
        cp16(&S[r][seg * 8], g + (size_t)r * ld + seg * 8);
    }
}

// ---------------- fragment loaders ----------------
// rowk A-frag: kw in words (0 or 8)
__device__ __forceinline__ void ldA_rowk(uint32_t* a, const uint32_t* As32, int M0, int kw) {
    const int l = threadIdx.x & 31;
    const uint32_t* p = As32 + (size_t)(M0 + (l >> 2)) * 20 + kw + (l & 3);
    a[0] = p[0]; a[1] = p[8 * 20]; a[2] = p[4]; a[3] = p[8 * 20 + 4];
}
__device__ __forceinline__ void ldB_rowk(uint32_t* b, const uint32_t* Bs32, int N0, int kw) {
    const int l = threadIdx.x & 31;
    const uint32_t* p = Bs32 + (size_t)(N0 + (l >> 2)) * 20 + kw + (l & 3);
    b[0] = p[0]; b[1] = p[4];
}
// krow A-frag via ldmatrix.trans: k16 in halves (0 or 16)
__device__ __forceinline__ void ldA_krow(uint32_t* a, const __nv_bfloat16* Sk, int M0, int k16) {
    const int l = threadIdx.x & 31;
    const int gq = l >> 3, lr = l & 7;
    const int krow = k16 + lr + ((gq & 2) ? 8 : 0);
    const int mcol = M0 + ((gq & 1) ? 8 : 0);
    uint32_t addr = (uint32_t)__cvta_generic_to_shared(Sk + (size_t)krow * 136 + mcol);
    asm volatile("ldmatrix.sync.aligned.m8n8.x4.trans.shared.b16 {%0,%1,%2,%3}, [%4];\n"
                 : "=r"(a[0]), "=r"(a[1]), "=r"(a[2]), "=r"(a[3]) : "r"(addr));
}
// krow B-frags for two n-tiles (N0, N0+8): out[0..1] tile N0, out[2..3] tile N0+8
__device__ __forceinline__ void ldB_krow_x2(uint32_t* b, const __nv_bfloat16* Sk, int N0, int k16) {
    const int l = threadIdx.x & 31;
    const int gq = l >> 3, lr = l & 7;
    const int krow = k16 + lr + ((gq & 1) ? 8 : 0);
    const int ncol = N0 + ((gq & 2) ? 8 : 0);
    uint32_t addr = (uint32_t)__cvta_generic_to_shared(Sk + (size_t)krow * 136 + ncol);
    asm volatile("ldmatrix.sync.aligned.m8n8.x4.trans.shared.b16 {%0,%1,%2,%3}, [%4];\n"
                 : "=r"(b[0]), "=r"(b[1]), "=r"(b[2]), "=r"(b[3]) : "r"(addr));
}

// ---------------- chunk compute variants (128x128x32) ----------------
__device__ __forceinline__ void comp_rowk_krow(const __nv_bfloat16 (*As)[40],
                                               const __nv_bfloat16 (*Bs)[136],
                                               float acc[4][4][4], int wm, int wn) {
    const uint32_t* As32 = (const uint32_t*)As;
#pragma unroll
    for (int ks = 0; ks < 2; ks++) {
        uint32_t a[4][4], bb[2][4];
#pragma unroll
        for (int i = 0; i < 4; i++) ldA_rowk(a[i], As32, wm * 64 + i * 16, ks * 8);
        ldB_krow_x2(bb[0], &Bs[0][0], wn * 32 + 0,  ks * 16);
        ldB_krow_x2(bb[1], &Bs[0][0], wn * 32 + 16, ks * 16);
#pragma unroll
        for (int i = 0; i < 4; i++)
#pragma unroll
            for (int j = 0; j < 4; j++)
                mma_bf16(acc[i][j], a[i], &bb[j >> 1][(j & 1) * 2]);
    }
}
__device__ __forceinline__ void comp_krow_krow(const __nv_bfloat16 (*As)[136],
                                               const __nv_bfloat16 (*Bs)[136],
                                               float acc[4][4][4], int wm, int wn) {
#pragma unroll
    for (int ks = 0; ks < 2; ks++) {
        uint32_t a[4][4], bb[2][4];
#pragma unroll
        for (int i = 0; i < 4; i++) ldA_krow(a[i], &As[0][0], wm * 64 + i * 16, ks * 16);
        ldB_krow_x2(bb[0], &Bs[0][0], wn * 32 + 0,  ks * 16);
        ldB_krow_x2(bb[1], &Bs[0][0], wn * 32 + 16, ks * 16);
#pragma unroll
        for (int i = 0; i < 4; i++)
#pragma unroll
            for (int j = 0; j < 4; j++)
                mma_bf16(acc[i][j], a[i], &bb[j >> 1][(j & 1) * 2]);
    }
}
__device__ __forceinline__ void comp_rowk_rowk(const __nv_bfloat16 (*As)[40],
                                               const __nv_bfloat16 (*Bs)[40],
                                               float acc[4][4][4], int wm, int wn) {
    const uint32_t* As32 = (const uint32_t*)As;
    const uint32_t* Bs32 = (const uint32_t*)Bs;
#pragma unroll
    for (int ks = 0; ks < 2; ks++) {
        uint32_t a[4][4], b[4][2];
#pragma unroll
        for (int i = 0; i < 4; i++) ldA_rowk(a[i], As32, wm * 64 + i * 16, ks * 8);
#pragma unroll
        for (int j = 0; j < 4; j++) ldB_rowk(b[j], Bs32, wn * 32 + j * 8, ks * 8);
#pragma unroll
        for (int i = 0; i < 4; i++)
#pragma unroll
            for (int j = 0; j < 4; j++) mma_bf16(acc[i][j], a[i], b[j]);
    }
}

// ---------------- weight convert ----------------
__global__ void convert_kernel(const float* __restrict__ src, __nv_bfloat16* __restrict__ dst,
                               int n4) {
    const int i = blockIdx.x * 256 + threadIdx.x;
    if (i < n4) {
        float4 v = ((const float4*)src)[i];
        uint2 o;
        o.x = pack_bf16(v.x, v.y);
        o.y = pack_bf16(v.z, v.w);
        ((uint2*)dst)[i] = o;
    }
}

// ---------------- GroupNorm -> bf16 h ----------------
__global__ void gn_kernel(const float* __restrict__ x,
                          const float* __restrict__ gamma,
                          const float* __restrict__ beta) {
    const int b = blockIdx.x >> 5;
    const int g = blockIdx.x & 31;
    const size_t base = ((size_t)b * CH + (size_t)g * CPG) * NSP;
    const float4* x4 = (const float4*)(x + base);
    uint2* h4 = (uint2*)(g_hb + base);
    const int tid = threadIdx.x;
    const int NV = CPG * NSP / 4;

    float s = 0.f, ss = 0.f;
    for (int i = tid; i < NV; i += 256) {
        float4 v = x4[i];
        s  += v.x + v.y + v.z + v.w;
        ss += v.x * v.x + v.y * v.y + v.z * v.z + v.w * v.w;
    }
    __shared__ float rs[256], rq[256];
    rs[tid] = s; rq[tid] = ss;
    __syncthreads();
    for (int o = 128; o > 0; o >>= 1) {
        if (tid < o) { rs[tid] += rs[tid + o]; rq[tid] += rq[tid + o]; }
        __syncthreads();
    }
    const float inv_n = 1.f / (float)(CPG * NSP);
    const float mean  = rs[0] * inv_n;
    const float var   = rq[0] * inv_n - mean * mean;
    const float rstd  = rsqrtf(var + 1e-5f);

    for (int i = tid; i < NV; i += 256) {
        const int c = g * CPG + (i >> 10);
        const float ga = gamma[c] * rstd;
        const float be = beta[c] - mean * ga;
        float4 v = x4[i];
        uint2 o;
        o.x = pack_bf16(v.x * ga + be, v.y * ga + be);
        o.y = pack_bf16(v.z * ga + be, v.w * ga + be);
        h4[i] = o;
    }
}

// ---------------- QKV: qkv[o,n] = W[o,:] @ h[:,n] + bias (bf16 out) ----------------
__global__ __launch_bounds__(256, 2) void qkv_kernel(const float* __restrict__ bias) {
    const int b = blockIdx.z;
    const int m0 = blockIdx.y * 128, n0 = blockIdx.x * 128;
    const __nv_bfloat16* W = g_wqkvb + (size_t)m0 * CH;
    const __nv_bfloat16* h = g_hb + (size_t)b * CH * NSP + n0;
    __shared__ __nv_bfloat16 As[2][128][40];
    __shared__ __nv_bfloat16 Bs[2][32][136];
    float acc[4][4][4] = {};
    const int lane = threadIdx.x & 31, wid = threadIdx.x >> 5;
    const int wm = wid >> 2, wn = wid & 3;

    stage_rowk(As[0], W, CH);
    stage_krow(Bs[0], h, NSP);
    CP_COMMIT();
    const int NC = CH / 32;
    for (int c = 0; c < NC; c++) {
        if (c + 1 < NC) {
            stage_rowk(As[(c + 1) & 1], W + (c + 1) * 32, CH);
            stage_krow(Bs[(c + 1) & 1], h + (size_t)(c + 1) * 32 * NSP, NSP);
        }
        CP_COMMIT();
        CP_WAIT1();
        __syncthreads();
        comp_rowk_krow(As[c & 1], Bs[c & 1], acc, wm, wn);
        __syncthreads();
    }
    __nv_bfloat16* out = g_qkvb + (size_t)b * 3 * CH * NSP;
#pragma unroll
    for (int i = 0; i < 4; i++) {
        const int m = m0 + wm * 64 + i * 16 + (lane >> 2);
        const float b0 = bias[m], b1 = bias[m + 8];
#pragma unroll
        for (int j = 0; j < 4; j++) {
            const int n = n0 + wn * 32 + j * 8 + 2 * (lane & 3);
            *(uint32_t*)(out + (size_t)m * NSP + n) =
                pack_bf16(acc[i][j][0] + b0, acc[i][j][1] + b0);
            *(uint32_t*)(out + (size_t)(m + 8) * NSP + n) =
                pack_bf16(acc[i][j][2] + b1, acc[i][j][3] + b1);
        }
    }
}

// ---------------- S = scale * Q^T K (fp32 out) ----------------
__global__ __launch_bounds__(256, 2) void s_kernel() {
    const int b = blockIdx.z;
    const int i0 = blockIdx.y * 128, j0 = blockIdx.x * 128;
    const __nv_bfloat16* Q  = g_qkvb + (size_t)b * 3 * CH * NSP + i0;
    const __nv_bfloat16* Kp = g_qkvb + ((size_t)b * 3 + 1) * CH * NSP + j0;
    __shared__ __nv_bfloat16 As[2][32][136];
    __shared__ __nv_bfloat16 Bs[2][32][136];
    float acc[4][4][4] = {};
    const int lane = threadIdx.x & 31, wid = threadIdx.x >> 5;
    const int wm = wid >> 2, wn = wid & 3;

    stage_krow(As[0], Q, NSP);
    stage_krow(Bs[0], Kp, NSP);
    CP_COMMIT();
    const int NC = CH / 32;
    for (int c = 0; c < NC; c++) {
        if (c + 1 < NC) {
            stage_krow(As[(c + 1) & 1], Q  + (size_t)(c + 1) * 32 * NSP, NSP);
            stage_krow(Bs[(c + 1) & 1], Kp + (size_t)(c + 1) * 32 * NSP, NSP);
        }
        CP_COMMIT();
        CP_WAIT1();
        __syncthreads();
        comp_krow_krow(As[c & 1], Bs[c & 1], acc, wm, wn);
        __syncthreads();
    }
    float* Sp = g_attn + (size_t)b * NSP * NSP;
#pragma unroll
    for (int i = 0; i < 4; i++) {
        const int m = i0 + wm * 64 + i * 16 + (lane >> 2);
#pragma unroll
        for (int j = 0; j < 4; j++) {
            const int n = j0 + wn * 32 + j * 8 + 2 * (lane & 3);
            *(float2*)(Sp + (size_t)m * NSP + n) =
                make_float2(acc[i][j][0] * SCALE, acc[i][j][1] * SCALE);
            *(float2*)(Sp + (size_t)(m + 8) * NSP + n) =
                make_float2(acc[i][j][2] * SCALE, acc[i][j][3] * SCALE);
        }
    }
}

// ---------------- softmax: read fp32 S, write bf16 P ----------------
__global__ void softmax_kernel() {
    const size_t row = (size_t)blockIdx.y * NSP + blockIdx.x;
    const float4* p = (const float4*)(g_attn + row * NSP);
    uint2* pb = (uint2*)(g_pb + row * NSP);
    const int tid = threadIdx.x;
    float4 v[4];
    float mx = -1e30f;
#pragma unroll
    for (int u = 0; u < 4; u++) {
        v[u] = p[tid + u * 256];
        mx = fmaxf(mx, fmaxf(fmaxf(v[u].x, v[u].y), fmaxf(v[u].z, v[u].w)));
    }
    __shared__ float red[256];
    red[tid] = mx;
    __syncthreads();
    for (int o = 128; o > 0; o >>= 1) {
        if (tid < o) red[tid] = fmaxf(red[tid], red[tid + o]);
        __syncthreads();
    }
    mx = red[0];
    __syncthreads();

    float s = 0.f;
#pragma unroll
    for (int u = 0; u < 4; u++) {
        v[u].x = __expf(v[u].x - mx); v[u].y = __expf(v[u].y - mx);
        v[u].z = __expf(v[u].z - mx); v[u].w = __expf(v[u].w - mx);
        s += v[u].x + v[u].y + v[u].z + v[u].w;
    }
    red[tid] = s;
    __syncthreads();
    for (int o = 128; o > 0; o >>= 1) {
        if (tid < o) red[tid] += red[tid + o];
        __syncthreads();
    }
    const float inv = 1.f / red[0];
#pragma unroll
    for (int u = 0; u < 4; u++) {
        uint2 o;
        o.x = pack_bf16(v[u].x * inv, v[u].y * inv);
        o.y = pack_bf16(v[u].z * inv, v[u].w * inv);
        pb[tid + u * 256] = o;
    }
}

// ---------------- AV: out2[c,i] = sum_j V[c,j] * P[i,j] (bf16 out) ----------------
__global__ __launch_bounds__(256, 2) void av_kernel() {
    const int b = blockIdx.z;
    const int m0 = blockIdx.y * 128, n0 = blockIdx.x * 128;   // m=c, n=i
    const __nv_bfloat16* V = g_qkvb + ((size_t)b * 3 + 2) * CH * NSP + (size_t)m0 * NSP;
    const __nv_bfloat16* P = g_pb + (size_t)b * NSP * NSP + (size_t)n0 * NSP;
    __shared__ __nv_bfloat16 As[2][128][40];
    __shared__ __nv_bfloat16 Bs[2][128][40];
    float acc[4][4][4] = {};
    const int lane = threadIdx.x & 31, wid = threadIdx.x >> 5;
    const int wm = wid >> 2, wn = wid & 3;

    stage_rowk(As[0], V, NSP);
    stage_rowk(Bs[0], P, NSP);
    CP_COMMIT();
    const int NC = NSP / 32;
    for (int c = 0; c < NC; c++) {
        if (c + 1 < NC) {
            stage_rowk(As[(c + 1) & 1], V + (c + 1) * 32, NSP);
            stage_rowk(Bs[(c + 1) & 1], P + (c + 1) * 32, NSP);
        }
        CP_COMMIT();
        CP_WAIT1();
        __syncthreads();
        comp_rowk_rowk(As[c & 1], Bs[c & 1], acc, wm, wn);
        __syncthreads();
    }
    __nv_bfloat16* out = g_out2b + (size_t)b * CH * NSP;
#pragma unroll
    for (int i = 0; i < 4; i++) {
        const int m = m0 + wm * 64 + i * 16 + (lane >> 2);
#pragma unroll
        for (int j = 0; j < 4; j++) {
            const int n = n0 + wn * 32 + j * 8 + 2 * (lane & 3);
            *(uint32_t*)(out + (size_t)m * NSP + n) = pack_bf16(acc[i][j][0], acc[i][j][1]);
            *(uint32_t*)(out + (size_t)(m + 8) * NSP + n) = pack_bf16(acc[i][j][2], acc[i][j][3]);
        }
    }
}

// ---------------- out: y = x + Wout @ out2 + b_out (fp32) ----------------
__global__ __launch_bounds__(256, 2) void out_kernel(const float* __restrict__ bias,
                                                     const float* __restrict__ x,
                                                     float* __restrict__ y) {
    const int b = blockIdx.z;
    const int m0 = blockIdx.y * 128, n0 = blockIdx.x * 128;
    const __nv_bfloat16* W = g_woutb + (size_t)m0 * CH;
    const __nv_bfloat16* hin = g_out2b + (size_t)b * CH * NSP + n0;
    __shared__ __nv_bfloat16 As[2][128][40];
    __shared__ __nv_bfloat16 Bs[2][32][136];
    float acc[4][4][4] = {};
    const int lane = threadIdx.x & 31, wid = threadIdx.x >> 5;
    const int wm = wid >> 2, wn = wid & 3;

    stage_rowk(As[0], W, CH);
    stage_krow(Bs[0], hin, NSP);
    CP_COMMIT();
    const int NC = CH / 32;
    for (int c = 0; c < NC; c++) {
        if (c + 1 < NC) {
            stage_rowk(As[(c + 1) & 1], W + (c + 1) * 32, CH);
            stage_krow(Bs[(c + 1) & 1], hin + (size_t)(c + 1) * 32 * NSP, NSP);
        }
        CP_COMMIT();
        CP_WAIT1();
        __syncthreads();
        comp_rowk_krow(As[c & 1], Bs[c & 1], acc, wm, wn);
        __syncthreads();
    }
#pragma unroll
    for (int i = 0; i < 4; i++) {
        const int m = m0 + wm * 64 + i * 16 + (lane >> 2);
        const float b0 = bias[m], b1 = bias[m + 8];
#pragma unroll
        for (int j = 0; j < 4; j++) {
            const int n = n0 + wn * 32 + j * 8 + 2 * (lane & 3);
            const size_t o0 = ((size_t)b * CH + m) * NSP + n;
            const size_t o1 = ((size_t)b * CH + m + 8) * NSP + n;
            float2 x0 = *(const float2*)(x + o0);
            float2 x1 = *(const float2*)(x + o1);
            *(float2*)(y + o0) =
                make_float2(acc[i][j][0] + b0 + x0.x, acc[i][j][1] + b0 + x0.y);
            *(float2*)(y + o1) =
                make_float2(acc[i][j][2] + b1 + x1.x, acc[i][j][3] + b1 + x1.y);
        }
    }
}

// ---------------- launch ----------------
extern "C" void kernel_launch(void* const* d_in, const int* in_sizes, int n_in,
                              void* d_out, int out_size) {
    const float* x     = (const float*)d_in[0];
    const float* gamma = (const float*)d_in[1];
    const float* beta  = (const float*)d_in[2];
    const float* w_qkv = (const float*)d_in[3];
    const float* b_qkv = (const float*)d_in[4];
    const float* w_out = (const float*)d_in[5];
    const float* b_out = (const float*)d_in[6];
    float* y = (float*)d_out;

    __nv_bfloat16* wqkvb; cudaGetSymbolAddress((void**)&wqkvb, g_wqkvb);
    __nv_bfloat16* woutb; cudaGetSymbolAddress((void**)&woutb, g_woutb);

    convert_kernel<<<(3 * CH * CH / 4 + 255) / 256, 256>>>(w_qkv, wqkvb, 3 * CH * CH / 4);
    convert_kernel<<<(CH * CH / 4 + 255) / 256, 256>>>(w_out, woutb, CH * CH / 4);
    gn_kernel<<<BATCH * NG, 256>>>(x, gamma, beta);
    qkv_kernel<<<dim3(NSP / 128, 3 * CH / 128, BATCH), 256>>>(b_qkv);
    s_kernel<<<dim3(NSP / 128, NSP / 128, BATCH), 256>>>();
    softmax_kernel<<<dim3(NSP, BATCH), 256>>>();
    av_kernel<<<dim3(NSP / 128, CH / 128, BATCH), 256>>>();
    out_kernel<<<dim3(NSP / 128, CH / 128, BATCH), 256>>>(b_out, x, y);
}

// round 4
// speedup vs baseline: 7.3747x; 1.0889x over previous
#include <cuda_runtime.h>
#include <cuda_bf16.h>
#include <cuda_fp16.h>
#include <math.h>
#include <stdint.h>

#define BATCH 8
#define CH    512
#define NSP   4096
#define NG    32
#define CPG   16
#define SCALE 0.044194173824159216f   // 1/sqrt(512)

// ---------------- scratch (device globals) ----------------
__device__ __nv_bfloat16 g_hb   [(size_t)BATCH * CH * NSP];       //  32 MB
__device__ __nv_bfloat16 g_qkvb [(size_t)BATCH * 3 * CH * NSP];   //  96 MB
__device__ __half        g_attn [(size_t)BATCH * NSP * NSP];      // 256 MB (fp16 logits)
__device__ __nv_bfloat16 g_pb   [(size_t)BATCH * NSP * NSP];      // 256 MB
__device__ __nv_bfloat16 g_out2b[(size_t)BATCH * CH * NSP];       //  32 MB
__device__ __nv_bfloat16 g_wqkvb[(size_t)3 * CH * CH];
__device__ __nv_bfloat16 g_woutb[(size_t)CH * CH];

// ---------------- small helpers ----------------
__device__ __forceinline__ uint32_t pack_bf16(float x, float y) {
    __nv_bfloat162 h = __floats2bfloat162_rn(x, y);
    return *reinterpret_cast<uint32_t*>(&h);
}
__device__ __forceinline__ uint32_t pack_f16(float x, float y) {
    __half2 h = __floats2half2_rn(x, y);
    return *reinterpret_cast<uint32_t*>(&h);
}
__device__ __forceinline__ void cp16(void* s, const void* g) {
    uint32_t sa = (uint32_t)__cvta_generic_to_shared(s);
    asm volatile("cp.async.cg.shared.global [%0], [%1], 16;\n" :: "r"(sa), "l"(g));
}
#define CP_COMMIT()  asm volatile("cp.async.commit_group;\n")
#define CP_WAIT1()   asm volatile("cp.async.wait_group 1;\n")

__device__ __forceinline__ void mma_bf16(float* d, const uint32_t* a, const uint32_t* b) {
    asm volatile(
        "mma.sync.aligned.m16n8k16.row.col.f32.bf16.bf16.f32 "
        "{%0,%1,%2,%3}, {%4,%5,%6,%7}, {%8,%9}, {%0,%1,%2,%3};\n"
        : "+f"(d[0]), "+f"(d[1]), "+f"(d[2]), "+f"(d[3])
        : "r"(a[0]), "r"(a[1]), "r"(a[2]), "r"(a[3]), "r"(b[0]), "r"(b[1]));
}

// ---------------- smem staging (layout-preserving) ----------------
__device__ __forceinline__ void stage_rowk(__nv_bfloat16 (*S)[40],
                                           const __nv_bfloat16* g, size_t ld) {
    const int t = threadIdx.x;
    const int seg = t & 3, r0 = t >> 2;
#pragma unroll
    for (int p = 0; p < 2; p++) {
        const int r = r0 + p * 64;
        cp16(&S[r][seg * 8], g + (size_t)r * ld + seg * 8);
    }
}
__device__ __forceinline__ void stage_krow(__nv_bfloat16 (*S)[136],
                                           const __nv_bfloat16* g, size_t ld) {
    const int t = threadIdx.x;
    const int seg = t & 15, r0 = t >> 4;
#pragma unroll
    for (int p = 0; p < 2; p++) {
        const int r = r0 + p * 16;
        cp16(&S[r][seg * 8], g + (size_t)r * ld + seg * 8);
    }
}

// ---------------- fragment loaders ----------------
__device__ __forceinline__ void ldA_rowk(uint32_t* a, const uint32_t* As32, int M0, int kw) {
    const int l = threadIdx.x & 31;
    const uint32_t* p = As32 + (size_t)(M0 + (l >> 2)) * 20 + kw + (l & 3);
    a[0] = p[0]; a[1] = p[8 * 20]; a[2] = p[4]; a[3] = p[8 * 20 + 4];
}
__device__ __forceinline__ void ldB_rowk(uint32_t* b, const uint32_t* Bs32, int N0, int kw) {
    const int l = threadIdx.x & 31;
    const uint32_t* p = Bs32 + (size_t)(N0 + (l >> 2)) * 20 + kw + (l & 3);
    b[0] = p[0]; b[1] = p[4];
}
__device__ __forceinline__ void ldA_krow(uint32_t* a, const __nv_bfloat16* Sk, int M0, int k16) {
    const int l = threadIdx.x & 31;
    const int gq = l >> 3, lr = l & 7;
    const int krow = k16 + lr + ((gq & 2) ? 8 : 0);
    const int mcol = M0 + ((gq & 1) ? 8 : 0);
    uint32_t addr = (uint32_t)__cvta_generic_to_shared(Sk + (size_t)krow * 136 + mcol);
    asm volatile("ldmatrix.sync.aligned.m8n8.x4.trans.shared.b16 {%0,%1,%2,%3}, [%4];\n"
                 : "=r"(a[0]), "=r"(a[1]), "=r"(a[2]), "=r"(a[3]) : "r"(addr));
}
__device__ __forceinline__ void ldB_krow_x2(uint32_t* b, const __nv_bfloat16* Sk, int N0, int k16) {
    const int l = threadIdx.x & 31;
    const int gq = l >> 3, lr = l & 7;
    const int krow = k16 + lr + ((gq & 1) ? 8 : 0);
    const int ncol = N0 + ((gq & 2) ? 8 : 0);
    uint32_t addr = (uint32_t)__cvta_generic_to_shared(Sk + (size_t)krow * 136 + ncol);
    asm volatile("ldmatrix.sync.aligned.m8n8.x4.trans.shared.b16 {%0,%1,%2,%3}, [%4];\n"
                 : "=r"(b[0]), "=r"(b[1]), "=r"(b[2]), "=r"(b[3]) : "r"(addr));
}

// ---------------- chunk compute variants (128x128x32) ----------------
__device__ __forceinline__ void comp_rowk_krow(const __nv_bfloat16 (*As)[40],
                                               const __nv_bfloat16 (*Bs)[136],
                                               float acc[4][4][4], int wm, int wn) {
    const uint32_t* As32 = (const uint32_t*)As;
#pragma unroll
    for (int ks = 0; ks < 2; ks++) {
        uint32_t a[4][4], bb[2][4];
#pragma unroll
        for (int i = 0; i < 4; i++) ldA_rowk(a[i], As32, wm * 64 + i * 16, ks * 8);
        ldB_krow_x2(bb[0], &Bs[0][0], wn * 32 + 0,  ks * 16);
        ldB_krow_x2(bb[1], &Bs[0][0], wn * 32 + 16, ks * 16);
#pragma unroll
        for (int i = 0; i < 4; i++)
#pragma unroll
            for (int j = 0; j < 4; j++)
                mma_bf16(acc[i][j], a[i], &bb[j >> 1][(j & 1) * 2]);
    }
}
__device__ __forceinline__ void comp_krow_krow(const __nv_bfloat16 (*As)[136],
                                               const __nv_bfloat16 (*Bs)[136],
                                               float acc[4][4][4], int wm, int wn) {
#pragma unroll
    for (int ks = 0; ks < 2; ks++) {
        uint32_t a[4][4], bb[2][4];
#pragma unroll
        for (int i = 0; i < 4; i++) ldA_krow(a[i], &As[0][0], wm * 64 + i * 16, ks * 16);
        ldB_krow_x2(bb[0], &Bs[0][0], wn * 32 + 0,  ks * 16);
        ldB_krow_x2(bb[1], &Bs[0][0], wn * 32 + 16, ks * 16);
#pragma unroll
        for (int i = 0; i < 4; i++)
#pragma unroll
            for (int j = 0; j < 4; j++)
                mma_bf16(acc[i][j], a[i], &bb[j >> 1][(j & 1) * 2]);
    }
}
__device__ __forceinline__ void comp_rowk_rowk(const __nv_bfloat16 (*As)[40],
                                               const __nv_bfloat16 (*Bs)[40],
                                               float acc[4][4][4], int wm, int wn) {
    const uint32_t* As32 = (const uint32_t*)As;
    const uint32_t* Bs32 = (const uint32_t*)Bs;
#pragma unroll
    for (int ks = 0; ks < 2; ks++) {
        uint32_t a[4][4], b[4][2];
#pragma unroll
        for (int i = 0; i < 4; i++) ldA_rowk(a[i], As32, wm * 64 + i * 16, ks * 8);
#pragma unroll
        for (int j = 0; j < 4; j++) ldB_rowk(b[j], Bs32, wn * 32 + j * 8, ks * 8);
#pragma unroll
        for (int i = 0; i < 4; i++)
#pragma unroll
            for (int j = 0; j < 4; j++) mma_bf16(acc[i][j], a[i], b[j]);
    }
}

// ---------------- weight convert ----------------
__global__ void convert_kernel(const float* __restrict__ src, __nv_bfloat16* __restrict__ dst,
                               int n4) {
    const int i = blockIdx.x * 256 + threadIdx.x;
    if (i < n4) {
        float4 v = ((const float4*)src)[i];
        uint2 o;
        o.x = pack_bf16(v.x, v.y);
        o.y = pack_bf16(v.z, v.w);
        ((uint2*)dst)[i] = o;
    }
}

// ---------------- GroupNorm -> bf16 h ----------------
__global__ void gn_kernel(const float* __restrict__ x,
                          const float* __restrict__ gamma,
                          const float* __restrict__ beta) {
    const int b = blockIdx.x >> 5;
    const int g = blockIdx.x & 31;
    const size_t base = ((size_t)b * CH + (size_t)g * CPG) * NSP;
    const float4* x4 = (const float4*)(x + base);
    uint2* h4 = (uint2*)(g_hb + base);
    const int tid = threadIdx.x;
    const int NV = CPG * NSP / 4;

    float s = 0.f, ss = 0.f;
    for (int i = tid; i < NV; i += 256) {
        float4 v = x4[i];
        s  += v.x + v.y + v.z + v.w;
        ss += v.x * v.x + v.y * v.y + v.z * v.z + v.w * v.w;
    }
    __shared__ float rs[256], rq[256];
    rs[tid] = s; rq[tid] = ss;
    __syncthreads();
    for (int o = 128; o > 0; o >>= 1) {
        if (tid < o) { rs[tid] += rs[tid + o]; rq[tid] += rq[tid + o]; }
        __syncthreads();
    }
    const float inv_n = 1.f / (float)(CPG * NSP);
    const float mean  = rs[0] * inv_n;
    const float var   = rq[0] * inv_n - mean * mean;
    const float rstd  = rsqrtf(var + 1e-5f);

    for (int i = tid; i < NV; i += 256) {
        const int c = g * CPG + (i >> 10);
        const float ga = gamma[c] * rstd;
        const float be = beta[c] - mean * ga;
        float4 v = x4[i];
        uint2 o;
        o.x = pack_bf16(v.x * ga + be, v.y * ga + be);
        o.y = pack_bf16(v.z * ga + be, v.w * ga + be);
        h4[i] = o;
    }
}

// ---------------- QKV (q-half scaled by SCALE in epilogue) ----------------
__global__ __launch_bounds__(256, 2) void qkv_kernel(const float* __restrict__ bias) {
    const int b = blockIdx.z;
    const int m0 = blockIdx.y * 128, n0 = blockIdx.x * 128;
    const __nv_bfloat16* W = g_wqkvb + (size_t)m0 * CH;
    const __nv_bfloat16* h = g_hb + (size_t)b * CH * NSP + n0;
    __shared__ __nv_bfloat16 As[3][128][40];
    __shared__ __nv_bfloat16 Bs[3][32][136];
    float acc[4][4][4] = {};
    const int lane = threadIdx.x & 31, wid = threadIdx.x >> 5;
    const int wm = wid >> 2, wn = wid & 3;
    const int NC = CH / 32;

    stage_rowk(As[0], W, CH);          stage_krow(Bs[0], h, NSP);              CP_COMMIT();
    stage_rowk(As[1], W + 32, CH);     stage_krow(Bs[1], h + 32 * NSP, NSP);   CP_COMMIT();
    int cur = 0, pre = 2;
    for (int c = 0; c < NC; c++) {
        CP_WAIT1();
        __syncthreads();
        if (c + 2 < NC) {
            stage_rowk(As[pre], W + (c + 2) * 32, CH);
            stage_krow(Bs[pre], h + (size_t)(c + 2) * 32 * NSP, NSP);
        }
        CP_COMMIT();
        comp_rowk_krow(As[cur], Bs[cur], acc, wm, wn);
        cur = (cur == 2) ? 0 : cur + 1;
        pre = (pre == 2) ? 0 : pre + 1;
    }
    const float mult = (blockIdx.y < 4) ? SCALE : 1.0f;   // q rows get the softmax scale
    __nv_bfloat16* out = g_qkvb + (size_t)b * 3 * CH * NSP;
#pragma unroll
    for (int i = 0; i < 4; i++) {
        const int m = m0 + wm * 64 + i * 16 + (lane >> 2);
        const float b0 = bias[m], b1 = bias[m + 8];
#pragma unroll
        for (int j = 0; j < 4; j++) {
            const int n = n0 + wn * 32 + j * 8 + 2 * (lane & 3);
            *(uint32_t*)(out + (size_t)m * NSP + n) =
                pack_bf16((acc[i][j][0] + b0) * mult, (acc[i][j][1] + b0) * mult);
            *(uint32_t*)(out + (size_t)(m + 8) * NSP + n) =
                pack_bf16((acc[i][j][2] + b1) * mult, (acc[i][j][3] + b1) * mult);
        }
    }
}

// ---------------- S = q^T k (scale pre-folded), fp16 out ----------------
__global__ __launch_bounds__(256, 2) void s_kernel() {
    const int b = blockIdx.z;
    const int i0 = blockIdx.y * 128, j0 = blockIdx.x * 128;
    const __nv_bfloat16* Q  = g_qkvb + (size_t)b * 3 * CH * NSP + i0;
    const __nv_bfloat16* Kp = g_qkvb + ((size_t)b * 3 + 1) * CH * NSP + j0;
    __shared__ __nv_bfloat16 As[3][32][136];
    __shared__ __nv_bfloat16 Bs[3][32][136];
    float acc[4][4][4] = {};
    const int lane = threadIdx.x & 31, wid = threadIdx.x >> 5;
    const int wm = wid >> 2, wn = wid & 3;
    const int NC = CH / 32;

    stage_krow(As[0], Q, NSP);            stage_krow(Bs[0], Kp, NSP);            CP_COMMIT();
    stage_krow(As[1], Q + 32 * NSP, NSP); stage_krow(Bs[1], Kp + 32 * NSP, NSP); CP_COMMIT();
    int cur = 0, pre = 2;
    for (int c = 0; c < NC; c++) {
        CP_WAIT1();
        __syncthreads();
        if (c + 2 < NC) {
            stage_krow(As[pre], Q  + (size_t)(c + 2) * 32 * NSP, NSP);
            stage_krow(Bs[pre], Kp + (size_t)(c + 2) * 32 * NSP, NSP);
        }
        CP_COMMIT();
        comp_krow_krow(As[cur], Bs[cur], acc, wm, wn);
        cur = (cur == 2) ? 0 : cur + 1;
        pre = (pre == 2) ? 0 : pre + 1;
    }
    __half* Sp = g_attn + (size_t)b * NSP * NSP;
#pragma unroll
    for (int i = 0; i < 4; i++) {
        const int m = i0 + wm * 64 + i * 16 + (lane >> 2);
#pragma unroll
        for (int j = 0; j < 4; j++) {
            const int n = j0 + wn * 32 + j * 8 + 2 * (lane & 3);
            *(uint32_t*)(Sp + (size_t)m * NSP + n) = pack_f16(acc[i][j][0], acc[i][j][1]);
            *(uint32_t*)(Sp + (size_t)(m + 8) * NSP + n) = pack_f16(acc[i][j][2], acc[i][j][3]);
        }
    }
}

// ---------------- softmax: read fp16 S, write bf16 P ----------------
__global__ void softmax_kernel() {
    const size_t row = (size_t)blockIdx.y * NSP + blockIdx.x;
    const uint4* p = (const uint4*)(g_attn + row * NSP);
    uint4* pb = (uint4*)(g_pb + row * NSP);
    const int tid = threadIdx.x;
    const int lane = tid & 31, wid = tid >> 5;

    uint4 raw[2];
    float v[16];
    float mx = -1e30f;
#pragma unroll
    for (int u = 0; u < 2; u++) {
        raw[u] = p[tid + u * 256];
        const uint32_t* w = (const uint32_t*)&raw[u];
#pragma unroll
        for (int q = 0; q < 4; q++) {
            float2 f = __half22float2(*(const __half2*)&w[q]);
            v[u * 8 + q * 2] = f.x; v[u * 8 + q * 2 + 1] = f.y;
            mx = fmaxf(mx, fmaxf(f.x, f.y));
        }
    }
#pragma unroll
    for (int o = 16; o > 0; o >>= 1) mx = fmaxf(mx, __shfl_xor_sync(~0u, mx, o));
    __shared__ float red[8];
    if (lane == 0) red[wid] = mx;
    __syncthreads();
    mx = fmaxf(fmaxf(fmaxf(red[0], red[1]), fmaxf(red[2], red[3])),
               fmaxf(fmaxf(red[4], red[5]), fmaxf(red[6], red[7])));

    float s = 0.f;
#pragma unroll
    for (int u = 0; u < 16; u++) { v[u] = __expf(v[u] - mx); s += v[u]; }
#pragma unroll
    for (int o = 16; o > 0; o >>= 1) s += __shfl_xor_sync(~0u, s, o);
    __shared__ float red2[8];
    if (lane == 0) red2[wid] = s;
    __syncthreads();
    s = (red2[0] + red2[1]) + (red2[2] + red2[3]) + (red2[4] + red2[5]) + (red2[6] + red2[7]);
    const float inv = 1.f / s;
#pragma unroll
    for (int u = 0; u < 2; u++) {
        uint4 o;
        uint32_t* w = (uint32_t*)&o;
#pragma unroll
        for (int q = 0; q < 4; q++)
            w[q] = pack_bf16(v[u * 8 + q * 2] * inv, v[u * 8 + q * 2 + 1] * inv);
        pb[tid + u * 256] = o;
    }
}

// ---------------- AV: out2[c,i] = sum_j V[c,j] * P[i,j] ----------------
// grid: (x = c-tile, y = i-tile, z = b)  -> consecutive CTAs share the P strip in L2
__global__ __launch_bounds__(256, 2) void av_kernel() {
    const int b = blockIdx.z;
    const int m0 = blockIdx.x * 128, n0 = blockIdx.y * 128;   // m=c, n=i
    const __nv_bfloat16* V = g_qkvb + ((size_t)b * 3 + 2) * CH * NSP + (size_t)m0 * NSP;
    const __nv_bfloat16* P = g_pb + (size_t)b * NSP * NSP + (size_t)n0 * NSP;
    __shared__ __nv_bfloat16 As[3][128][40];
    __shared__ __nv_bfloat16 Bs[3][128][40];
    float acc[4][4][4] = {};
    const int lane = threadIdx.x & 31, wid = threadIdx.x >> 5;
    const int wm = wid >> 2, wn = wid & 3;
    const int NC = NSP / 32;

    stage_rowk(As[0], V, NSP);      stage_rowk(Bs[0], P, NSP);      CP_COMMIT();
    stage_rowk(As[1], V + 32, NSP); stage_rowk(Bs[1], P + 32, NSP); CP_COMMIT();
    int cur = 0, pre = 2;
    for (int c = 0; c < NC; c++) {
        CP_WAIT1();
        __syncthreads();
        if (c + 2 < NC) {
            stage_rowk(As[pre], V + (c + 2) * 32, NSP);
            stage_rowk(Bs[pre], P + (c + 2) * 32, NSP);
        }
        CP_COMMIT();
        comp_rowk_rowk(As[cur], Bs[cur], acc, wm, wn);
        cur = (cur == 2) ? 0 : cur + 1;
        pre = (pre == 2) ? 0 : pre + 1;
    }
    __nv_bfloat16* out = g_out2b + (size_t)b * CH * NSP;
#pragma unroll
    for (int i = 0; i < 4; i++) {
        const int m = m0 + wm * 64 + i * 16 + (lane >> 2);
#pragma unroll
        for (int j = 0; j < 4; j++) {
            const int n = n0 + wn * 32 + j * 8 + 2 * (lane & 3);
            *(uint32_t*)(out + (size_t)m * NSP + n) = pack_bf16(acc[i][j][0], acc[i][j][1]);
            *(uint32_t*)(out + (size_t)(m + 8) * NSP + n) = pack_bf16(acc[i][j][2], acc[i][j][3]);
        }
    }
}

// ---------------- out: y = x + Wout @ out2 + b_out (fp32) ----------------
__global__ __launch_bounds__(256, 2) void out_kernel(const float* __restrict__ bias,
                                                     const float* __restrict__ x,
                                                     float* __restrict__ y) {
    const int b = blockIdx.z;
    const int m0 = blockIdx.y * 128, n0 = blockIdx.x * 128;
    const __nv_bfloat16* W = g_woutb + (size_t)m0 * CH;
    const __nv_bfloat16* hin = g_out2b + (size_t)b * CH * NSP + n0;
    __shared__ __nv_bfloat16 As[3][128][40];
    __shared__ __nv_bfloat16 Bs[3][32][136];
    float acc[4][4][4] = {};
    const int lane = threadIdx.x & 31, wid = threadIdx.x >> 5;
    const int wm = wid >> 2, wn = wid & 3;
    const int NC = CH / 32;

    stage_rowk(As[0], W, CH);      stage_krow(Bs[0], hin, NSP);            CP_COMMIT();
    stage_rowk(As[1], W + 32, CH); stage_krow(Bs[1], hin + 32 * NSP, NSP); CP_COMMIT();
    int cur = 0, pre = 2;
    for (int c = 0; c < NC; c++) {
        CP_WAIT1();
        __syncthreads();
        if (c + 2 < NC) {
            stage_rowk(As[pre], W + (c + 2) * 32, CH);
            stage_krow(Bs[pre], hin + (size_t)(c + 2) * 32 * NSP, NSP);
        }
        CP_COMMIT();
        comp_rowk_krow(As[cur], Bs[cur], acc, wm, wn);
        cur = (cur == 2) ? 0 : cur + 1;
        pre = (pre == 2) ? 0 : pre + 1;
    }
#pragma unroll
    for (int i = 0; i < 4; i++) {
        const int m = m0 + wm * 64 + i * 16 + (lane >> 2);
        const float b0 = bias[m], b1 = bias[m + 8];
#pragma unroll
        for (int j = 0; j < 4; j++) {
            const int n = n0 + wn * 32 + j * 8 + 2 * (lane & 3);
            const size_t o0 = ((size_t)b * CH + m) * NSP + n;
            const size_t o1 = ((size_t)b * CH + m + 8) * NSP + n;
            float2 x0 = *(const float2*)(x + o0);
            float2 x1 = *(const float2*)(x + o1);
            *(float2*)(y + o0) =
                make_float2(acc[i][j][0] + b0 + x0.x, acc[i][j][1] + b0 + x0.y);
            *(float2*)(y + o1) =
                make_float2(acc[i][j][2] + b1 + x1.x, acc[i][j][3] + b1 + x1.y);
        }
    }
}

// ---------------- launch ----------------
extern "C" void kernel_launch(void* const* d_in, const int* in_sizes, int n_in,
                              void* d_out, int out_size) {
    const float* x     = (const float*)d_in[0];
    const float* gamma = (const float*)d_in[1];
    const float* beta  = (const float*)d_in[2];
    const float* w_qkv = (const float*)d_in[3];
    const float* b_qkv = (const float*)d_in[4];
    const float* w_out = (const float*)d_in[5];
    const float* b_out = (const float*)d_in[6];
    float* y = (float*)d_out;

    __nv_bfloat16* wqkvb; cudaGetSymbolAddress((void**)&wqkvb, g_wqkvb);
    __nv_bfloat16* woutb; cudaGetSymbolAddress((void**)&woutb, g_woutb);

    convert_kernel<<<(3 * CH * CH / 4 + 255) / 256, 256>>>(w_qkv, wqkvb, 3 * CH * CH / 4);
    convert_kernel<<<(CH * CH / 4 + 255) / 256, 256>>>(w_out, woutb, CH * CH / 4);
    gn_kernel<<<BATCH * NG, 256>>>(x, gamma, beta);
    qkv_kernel<<<dim3(NSP / 128, 3 * CH / 128, BATCH), 256>>>(b_qkv);
    s_kernel<<<dim3(NSP / 128, NSP / 128, BATCH), 256>>>();
    softmax_kernel<<<dim3(NSP, BATCH), 256>>>();
    av_kernel<<<dim3(CH / 128, NSP / 128, BATCH), 256>>>();
    out_kernel<<<dim3(NSP / 128, CH / 128, BATCH), 256>>>(b_out, x, y);
}

// round 6
// speedup vs baseline: 7.8341x; 1.0623x over previous
#include <cuda_runtime.h>
#include <cuda_bf16.h>
#include <cuda_fp16.h>
#include <math.h>
#include <stdint.h>

#define BATCH 8
#define CH    512
#define NSP   4096
#define SCALE 0.044194173824159216f   // 1/sqrt(512)

// rowk buffer: 128 rows x 64 halves, stride 72 halves (144B)  -> 18432 B/stage
// krow buffer:  64 rows x 128 halves, stride 136 halves (272B) -> 17408 B/stage
#define ROWK_B 18432
#define KROW_B 17408

// ---------------- scratch (device globals) ----------------
__device__ __nv_bfloat16 g_hb   [(size_t)BATCH * CH * NSP];       //  32 MB  [b][c][n]
__device__ __nv_bfloat16 g_qkvb [(size_t)BATCH * 3 * CH * NSP];   //  96 MB  [b][o][n]
__device__ __half        g_attn [(size_t)BATCH * NSP * NSP];      // 256 MB  logits fp16
__device__ __nv_bfloat16 g_pb   [(size_t)BATCH * NSP * NSP];      // 256 MB  softmax bf16
__device__ __nv_bfloat16 g_out2b[(size_t)BATCH * CH * NSP];       //  32 MB  [b][c][n]
__device__ __nv_bfloat16 g_wqkvb[(size_t)3 * CH * CH];
__device__ __nv_bfloat16 g_woutb[(size_t)CH * CH];

// ---------------- helpers ----------------
__device__ __forceinline__ uint32_t pack_bf16(float x, float y) {
    __nv_bfloat162 h = __floats2bfloat162_rn(x, y);
    return *reinterpret_cast<uint32_t*>(&h);
}
__device__ __forceinline__ uint32_t pack_f16(float x, float y) {
    __half2 h = __floats2half2_rn(x, y);
    return *reinterpret_cast<uint32_t*>(&h);
}
__device__ __forceinline__ void cp16(uint32_t s, const void* g) {
    asm volatile("cp.async.cg.shared.global [%0], [%1], 16;\n" :: "r"(s), "l"(g));
}
#define CP_COMMIT()  asm volatile("cp.async.commit_group;\n")
#define CP_WAIT1()   asm volatile("cp.async.wait_group 1;\n" ::: "memory")

__device__ __forceinline__ void mma_bf16(float* d, const uint32_t* a, const uint32_t* b) {
    asm volatile(
        "mma.sync.aligned.m16n8k16.row.col.f32.bf16.bf16.f32 "
        "{%0,%1,%2,%3}, {%4,%5,%6,%7}, {%8,%9}, {%0,%1,%2,%3};\n"
        : "+f"(d[0]), "+f"(d[1]), "+f"(d[2]), "+f"(d[3])
        : "r"(a[0]), "r"(a[1]), "r"(a[2]), "r"(a[3]), "r"(b[0]), "r"(b[1]));
}
__device__ __forceinline__ void ldm_x4(uint32_t* r, uint32_t addr) {
    asm volatile("ldmatrix.sync.aligned.m8n8.x4.shared.b16 {%0,%1,%2,%3}, [%4];\n"
                 : "=r"(r[0]), "=r"(r[1]), "=r"(r[2]), "=r"(r[3]) : "r"(addr));
}
__device__ __forceinline__ void ldm_x4t(uint32_t* r, uint32_t addr) {
    asm volatile("ldmatrix.sync.aligned.m8n8.x4.trans.shared.b16 {%0,%1,%2,%3}, [%4];\n"
                 : "=r"(r[0]), "=r"(r[1]), "=r"(r[2]), "=r"(r[3]) : "r"(addr));
}

// ---------------- smem staging (64-k chunks) ----------------
// rowk: 128 rows x 64 halves (1024 x 16B chunks)
__device__ __forceinline__ void stage_rowk(uint32_t sb, const __nv_bfloat16* g, size_t ld) {
    const int t = threadIdx.x;
#pragma unroll
    for (int p = 0; p < 4; p++) {
        const int idx = t + p * 256;
        const int row = idx >> 3, c = idx & 7;
        cp16(sb + row * 144 + c * 16, g + (size_t)row * ld + c * 8);
    }
}
// krow: 64 rows x 128 halves (1024 x 16B chunks)
__device__ __forceinline__ void stage_krow(uint32_t sb, const __nv_bfloat16* g, size_t ld) {
    const int t = threadIdx.x;
#pragma unroll
    for (int p = 0; p < 4; p++) {
        const int idx = t + p * 256;
        const int row = idx >> 4, c = idx & 15;
        cp16(sb + row * 272 + c * 16, g + (size_t)row * ld + c * 8);
    }
}

// ---------------- ldmatrix fragment loaders ----------------
// A from rowk [m][k] (stride 72 halves): a0..a3 = (m0,k0),(m8,k0),(m0,k8),(m8,k8)
__device__ __forceinline__ void ldA_rowk(uint32_t* a, uint32_t base, int M0, int kk) {
    const int l = threadIdx.x & 31;
    const uint32_t addr = base + (uint32_t)(M0 + (l & 15)) * 144
                               + (uint32_t)(kk + ((l >> 4) << 3)) * 2;
    ldm_x4(a, addr);
}
// B from rowk [n][k]: r0,r1 = b0,b1 for n-tile N0; r2,r3 for n-tile N0+8
__device__ __forceinline__ void ldB_rowk(uint32_t* b, uint32_t base, int N0, int kk) {
    const int l = threadIdx.x & 31;
    const uint32_t addr = base + (uint32_t)(N0 + ((l >> 4) << 3) + (l & 7)) * 144
                               + (uint32_t)(kk + (((l >> 3) & 1) << 3)) * 2;
    ldm_x4(b, addr);
}
// A from krow [k][m] (stride 136 halves), trans
__device__ __forceinline__ void ldA_krow(uint32_t* a, uint32_t base, int M0, int kk) {
    const int l = threadIdx.x & 31;
    const int gq = l >> 3, lr = l & 7;
    const uint32_t addr = base + (uint32_t)(kk + lr + ((gq & 2) ? 8 : 0)) * 272
                               + (uint32_t)(M0 + ((gq & 1) ? 8 : 0)) * 2;
    ldm_x4t(a, addr);
}
// B from krow [k][n], trans: r0,r1 tile N0; r2,r3 tile N0+8
__device__ __forceinline__ void ldB_krow(uint32_t* b, uint32_t base, int N0, int kk) {
    const int l = threadIdx.x & 31;
    const int gq = l >> 3, lr = l & 7;
    const uint32_t addr = base + (uint32_t)(kk + lr + ((gq & 1) ? 8 : 0)) * 272
                               + (uint32_t)(N0 + ((gq & 2) ? 8 : 0)) * 2;
    ldm_x4t(b, addr);
}

// ---------------- chunk compute (128x128x64) ----------------
__device__ __forceinline__ void comp_rowk_krow(uint32_t A, uint32_t B,
                                               float acc[4][4][4], int wm, int wn) {
#pragma unroll
    for (int ks = 0; ks < 4; ks++) {
        uint32_t a[4][4], bb[2][4];
#pragma unroll
        for (int i = 0; i < 4; i++) ldA_rowk(a[i], A, wm * 64 + i * 16, ks * 16);
        ldB_krow(bb[0], B, wn * 32 + 0,  ks * 16);
        ldB_krow(bb[1], B, wn * 32 + 16, ks * 16);
#pragma unroll
        for (int i = 0; i < 4; i++)
#pragma unroll
            for (int j = 0; j < 4; j++)
                mma_bf16(acc[i][j], a[i], &bb[j >> 1][(j & 1) * 2]);
    }
}
__device__ __forceinline__ void comp_krow_krow(uint32_t A, uint32_t B,
                                               float acc[4][4][4], int wm, int wn) {
#pragma unroll
    for (int ks = 0; ks < 4; ks++) {
        uint32_t a[4][4], bb[2][4];
#pragma unroll
        for (int i = 0; i < 4; i++) ldA_krow(a[i], A, wm * 64 + i * 16, ks * 16);
        ldB_krow(bb[0], B, wn * 32 + 0,  ks * 16);
        ldB_krow(bb[1], B, wn * 32 + 16, ks * 16);
#pragma unroll
        for (int i = 0; i < 4; i++)
#pragma unroll
            for (int j = 0; j < 4; j++)
                mma_bf16(acc[i][j], a[i], &bb[j >> 1][(j & 1) * 2]);
    }
}
__device__ __forceinline__ void comp_rowk_rowk(uint32_t A, uint32_t B,
                                               float acc[4][4][4], int wm, int wn) {
#pragma unroll
    for (int ks = 0; ks < 4; ks++) {
        uint32_t a[4][4], bb[2][4];
#pragma unroll
        for (int i = 0; i < 4; i++) ldA_rowk(a[i], A, wm * 64 + i * 16, ks * 16);
        ldB_rowk(bb[0], B, wn * 32 + 0,  ks * 16);
        ldB_rowk(bb[1], B, wn * 32 + 16, ks * 16);
#pragma unroll
        for (int i = 0; i < 4; i++)
#pragma unroll
            for (int j = 0; j < 4; j++)
                mma_bf16(acc[i][j], a[i], &bb[j >> 1][(j & 1) * 2]);
    }
}

// ---------------- weight convert ----------------
__global__ void convert_kernel(const float* __restrict__ src,
                               __nv_bfloat16* __restrict__ dst, int n4) {
    const int i = blockIdx.x * 256 + threadIdx.x;
    if (i < n4) {
        float4 v = ((const float4*)src)[i];
        uint2 o;
        o.x = pack_bf16(v.x, v.y);
        o.y = pack_bf16(v.z, v.w);
        ((uint2*)dst)[i] = o;
    }
}

// ---------------- GroupNorm -> bf16 h [b][c][n] ----------------
__global__ void gn_kernel(const float* __restrict__ x,
                          const float* __restrict__ gamma,
                          const float* __restrict__ beta) {
    const int b = blockIdx.x >> 5;
    const int g = blockIdx.x & 31;
    const size_t base = ((size_t)b * CH + (size_t)g * 16) * NSP;
    const float4* x4 = (const float4*)(x + base);
    uint2* h4 = (uint2*)(g_hb + base);
    const int tid = threadIdx.x;
    const int NV = 16 * NSP / 4;

    float s = 0.f, ss = 0.f;
    for (int i = tid; i < NV; i += 256) {
        float4 v = x4[i];
        s  += v.x + v.y + v.z + v.w;
        ss += v.x * v.x + v.y * v.y + v.z * v.z + v.w * v.w;
    }
    __shared__ float rs[256], rq[256];
    rs[tid] = s; rq[tid] = ss;
    __syncthreads();
    for (int o = 128; o > 0; o >>= 1) {
        if (tid < o) { rs[tid] += rs[tid + o]; rq[tid] += rq[tid + o]; }
        __syncthreads();
    }
    const float inv_n = 1.f / (float)(16 * NSP);
    const float mean  = rs[0] * inv_n;
    const float var   = rq[0] * inv_n - mean * mean;
    const float rstd  = rsqrtf(var + 1e-5f);

    for (int i = tid; i < NV; i += 256) {
        const int c = g * 16 + (i >> 10);
        const float ga = gamma[c] * rstd;
        const float be = beta[c] - mean * ga;
        float4 v = x4[i];
        uint2 o;
        o.x = pack_bf16(v.x * ga + be, v.y * ga + be);
        o.y = pack_bf16(v.z * ga + be, v.w * ga + be);
        h4[i] = o;
    }
}

// ---------------- QKV (q rows scaled by SCALE in epilogue) ----------------
__global__ __launch_bounds__(256, 2) void qkv_kernel(const float* __restrict__ bias) {
    const int b = blockIdx.z;
    const int m0 = blockIdx.y * 128, n0 = blockIdx.x * 128;
    const __nv_bfloat16* W = g_wqkvb + (size_t)m0 * CH;
    const __nv_bfloat16* h = g_hb + (size_t)b * CH * NSP + n0;
    extern __shared__ __align__(16) char smem[];
    const uint32_t sA = (uint32_t)__cvta_generic_to_shared(smem);
    const uint32_t sB = sA + 3 * ROWK_B;
    float acc[4][4][4] = {};
    const int lane = threadIdx.x & 31, wid = threadIdx.x >> 5;
    const int wm = wid >> 2, wn = wid & 3;

    stage_rowk(sA, W, CH);              stage_krow(sB, h, NSP);                    CP_COMMIT();
    stage_rowk(sA + ROWK_B, W + 64, CH); stage_krow(sB + KROW_B, h + 64 * NSP, NSP); CP_COMMIT();
    for (int c = 0; c < 8; c++) {
        CP_WAIT1();
        __syncthreads();
        if (c + 2 < 8) {
            const int s2 = (c + 2) % 3;
            stage_rowk(sA + s2 * ROWK_B, W + (c + 2) * 64, CH);
            stage_krow(sB + s2 * KROW_B, h + (size_t)(c + 2) * 64 * NSP, NSP);
        }
        CP_COMMIT();
        const int cs = c % 3;
        comp_rowk_krow(sA + cs * ROWK_B, sB + cs * KROW_B, acc, wm, wn);
    }
    const float mult = (blockIdx.y < 4) ? SCALE : 1.0f;
    __nv_bfloat16* out = g_qkvb + (size_t)b * 3 * CH * NSP;
#pragma unroll
    for (int i = 0; i < 4; i++) {
        const int m = m0 + wm * 64 + i * 16 + (lane >> 2);
        const float b0 = bias[m], b1 = bias[m + 8];
#pragma unroll
        for (int j = 0; j < 4; j++) {
            const int n = n0 + wn * 32 + j * 8 + 2 * (lane & 3);
            *(uint32_t*)(out + (size_t)m * NSP + n) =
                pack_bf16((acc[i][j][0] + b0) * mult, (acc[i][j][1] + b0) * mult);
            *(uint32_t*)(out + (size_t)(m + 8) * NSP + n) =
                pack_bf16((acc[i][j][2] + b1) * mult, (acc[i][j][3] + b1) * mult);
        }
    }
}

// ---------------- S = q^T k (scale pre-folded), fp16 out ----------------
__global__ __launch_bounds__(256, 2) void s_kernel() {
    const int b = blockIdx.z;
    const int i0 = blockIdx.y * 128, j0 = blockIdx.x * 128;
    const __nv_bfloat16* Q  = g_qkvb + (size_t)b * 3 * CH * NSP + i0;
    const __nv_bfloat16* Kp = g_qkvb + ((size_t)b * 3 + 1) * CH * NSP + j0;
    extern __shared__ __align__(16) char smem[];
    const uint32_t sA = (uint32_t)__cvta_generic_to_shared(smem);
    const uint32_t sB = sA + 3 * KROW_B;
    float acc[4][4][4] = {};
    const int lane = threadIdx.x & 31, wid = threadIdx.x >> 5;
    const int wm = wid >> 2, wn = wid & 3;

    stage_krow(sA, Q, NSP);                    stage_krow(sB, Kp, NSP);                    CP_COMMIT();
    stage_krow(sA + KROW_B, Q + 64 * NSP, NSP); stage_krow(sB + KROW_B, Kp + 64 * NSP, NSP); CP_COMMIT();
    for (int c = 0; c < 8; c++) {
        CP_WAIT1();
        __syncthreads();
        if (c + 2 < 8) {
            const int s2 = (c + 2) % 3;
            stage_krow(sA + s2 * KROW_B, Q  + (size_t)(c + 2) * 64 * NSP, NSP);
            stage_krow(sB + s2 * KROW_B, Kp + (size_t)(c + 2) * 64 * NSP, NSP);
        }
        CP_COMMIT();
        const int cs = c % 3;
        comp_krow_krow(sA + cs * KROW_B, sB + cs * KROW_B, acc, wm, wn);
    }
    __half* Sp = g_attn + (size_t)b * NSP * NSP;
#pragma unroll
    for (int i = 0; i < 4; i++) {
        const int m = i0 + wm * 64 + i * 16 + (lane >> 2);
#pragma unroll
        for (int j = 0; j < 4; j++) {
            const int n = j0 + wn * 32 + j * 8 + 2 * (lane & 3);
            *(uint32_t*)(Sp + (size_t)m * NSP + n) = pack_f16(acc[i][j][0], acc[i][j][1]);
            *(uint32_t*)(Sp + (size_t)(m + 8) * NSP + n) = pack_f16(acc[i][j][2], acc[i][j][3]);
        }
    }
}

// ---------------- softmax: read fp16 S, write bf16 P ----------------
__global__ void softmax_kernel() {
    const size_t row = (size_t)blockIdx.y * NSP + blockIdx.x;
    const uint4* p = (const uint4*)(g_attn + row * NSP);
    uint4* pb = (uint4*)(g_pb + row * NSP);
    const int tid = threadIdx.x;
    const int lane = tid & 31, wid = tid >> 5;

    uint4 raw[2];
    float v[16];
    float mx = -1e30f;
#pragma unroll
    for (int u = 0; u < 2; u++) {
        raw[u] = p[tid + u * 256];
        const uint32_t* w = (const uint32_t*)&raw[u];
#pragma unroll
        for (int q = 0; q < 4; q++) {
            float2 f = __half22float2(*(const __half2*)&w[q]);
            v[u * 8 + q * 2] = f.x; v[u * 8 + q * 2 + 1] = f.y;
            mx = fmaxf(mx, fmaxf(f.x, f.y));
        }
    }
#pragma unroll
    for (int o = 16; o > 0; o >>= 1) mx = fmaxf(mx, __shfl_xor_sync(~0u, mx, o));
    __shared__ float red[8];
    if (lane == 0) red[wid] = mx;
    __syncthreads();
    mx = fmaxf(fmaxf(fmaxf(red[0], red[1]), fmaxf(red[2], red[3])),
               fmaxf(fmaxf(red[4], red[5]), fmaxf(red[6], red[7])));

    float s = 0.f;
#pragma unroll
    for (int u = 0; u < 16; u++) { v[u] = __expf(v[u] - mx); s += v[u]; }
#pragma unroll
    for (int o = 16; o > 0; o >>= 1) s += __shfl_xor_sync(~0u, s, o);
    __shared__ float red2[8];
    if (lane == 0) red2[wid] = s;
    __syncthreads();
    s = (red2[0] + red2[1]) + (red2[2] + red2[3]) + (red2[4] + red2[5]) + (red2[6] + red2[7]);
    const float inv = 1.f / s;
#pragma unroll
    for (int u = 0; u < 2; u++) {
        uint4 o;
        uint32_t* w = (uint32_t*)&o;
#pragma unroll
        for (int q = 0; q < 4; q++)
            w[q] = pack_bf16(v[u * 8 + q * 2] * inv, v[u * 8 + q * 2 + 1] * inv);
        pb[tid + u * 256] = o;
    }
}

// ---------------- AV: out2[c,i] = sum_j V[c,j] * P[i,j] ----------------
__global__ __launch_bounds__(256, 2) void av_kernel() {
    const int b = blockIdx.z;
    const int m0 = blockIdx.x * 128, n0 = blockIdx.y * 128;   // m=c, n=i
    const __nv_bfloat16* V = g_qkvb + ((size_t)b * 3 + 2) * CH * NSP + (size_t)m0 * NSP;
    const __nv_bfloat16* P = g_pb + (size_t)b * NSP * NSP + (size_t)n0 * NSP;
    extern __shared__ __align__(16) char smem[];
    const uint32_t sA = (uint32_t)__cvta_generic_to_shared(smem);
    const uint32_t sB = sA + 3 * ROWK_B;
    float acc[4][4][4] = {};
    const int lane = threadIdx.x & 31, wid = threadIdx.x >> 5;
    const int wm = wid >> 2, wn = wid & 3;

    stage_rowk(sA, V, NSP);              stage_rowk(sB, P, NSP);              CP_COMMIT();
    stage_rowk(sA + ROWK_B, V + 64, NSP); stage_rowk(sB + ROWK_B, P + 64, NSP); CP_COMMIT();
    for (int c = 0; c < 64; c++) {
        CP_WAIT1();
        __syncthreads();
        if (c + 2 < 64) {
            const int s2 = (c + 2) % 3;
            stage_rowk(sA + s2 * ROWK_B, V + (c + 2) * 64, NSP);
            stage_rowk(sB + s2 * ROWK_B, P + (c + 2) * 64, NSP);
        }
        CP_COMMIT();
        const int cs = c % 3;
        comp_rowk_rowk(sA + cs * ROWK_B, sB + cs * ROWK_B, acc, wm, wn);
    }
    __nv_bfloat16* out = g_out2b + (size_t)b * CH * NSP;
#pragma unroll
    for (int i = 0; i < 4; i++) {
        const int m = m0 + wm * 64 + i * 16 + (lane >> 2);
#pragma unroll
        for (int j = 0; j < 4; j++) {
            const int n = n0 + wn * 32 + j * 8 + 2 * (lane & 3);
            *(uint32_t*)(out + (size_t)m * NSP + n) = pack_bf16(acc[i][j][0], acc[i][j][1]);
            *(uint32_t*)(out + (size_t)(m + 8) * NSP + n) = pack_bf16(acc[i][j][2], acc[i][j][3]);
        }
    }
}

// ---------------- out: y = x + Wout @ out2 + b_out (fp32) ----------------
__global__ __launch_bounds__(256, 2) void out_kernel(const float* __restrict__ bias,
                                                     const float* __restrict__ x,
                                                     float* __restrict__ y) {
    const int b = blockIdx.z;
    const int m0 = blockIdx.y * 128, n0 = blockIdx.x * 128;
    const __nv_bfloat16* W = g_woutb + (size_t)m0 * CH;
    const __nv_bfloat16* hin = g_out2b + (size_t)b * CH * NSP + n0;
    extern __shared__ __align__(16) char smem[];
    const uint32_t sA = (uint32_t)__cvta_generic_to_shared(smem);
    const uint32_t sB = sA + 3 * ROWK_B;
    float acc[4][4][4] = {};
    const int lane = threadIdx.x & 31, wid = threadIdx.x >> 5;
    const int wm = wid >> 2, wn = wid & 3;

    stage_rowk(sA, W, CH);              stage_krow(sB, hin, NSP);                    CP_COMMIT();
    stage_rowk(sA + ROWK_B, W + 64, CH); stage_krow(sB + KROW_B, hin + 64 * NSP, NSP); CP_COMMIT();
    for (int c = 0; c < 8; c++) {
        CP_WAIT1();
        __syncthreads();
        if (c + 2 < 8) {
            const int s2 = (c + 2) % 3;
            stage_rowk(sA + s2 * ROWK_B, W + (c + 2) * 64, CH);
            stage_krow(sB + s2 * KROW_B, hin + (size_t)(c + 2) * 64 * NSP, NSP);
        }
        CP_COMMIT();
        const int cs = c % 3;
        comp_rowk_krow(sA + cs * ROWK_B, sB + cs * KROW_B, acc, wm, wn);
    }
#pragma unroll
    for (int i = 0; i < 4; i++) {
        const int m = m0 + wm * 64 + i * 16 + (lane >> 2);
        const float b0 = bias[m], b1 = bias[m + 8];
#pragma unroll
        for (int j = 0; j < 4; j++) {
            const int n = n0 + wn * 32 + j * 8 + 2 * (lane & 3);
            const size_t o0 = ((size_t)b * CH + m) * NSP + n;
            const size_t o1 = ((size_t)b * CH + m + 8) * NSP + n;
            float2 x0 = *(const float2*)(x + o0);
            float2 x1 = *(const float2*)(x + o1);
            *(float2*)(y + o0) =
                make_float2(acc[i][j][0] + b0 + x0.x, acc[i][j][1] + b0 + x0.y);
            *(float2*)(y + o1) =
                make_float2(acc[i][j][2] + b1 + x1.x, acc[i][j][3] + b1 + x1.y);
        }
    }
}

// ---------------- launch ----------------
extern "C" void kernel_launch(void* const* d_in, const int* in_sizes, int n_in,
                              void* d_out, int out_size) {
    const float* x     = (const float*)d_in[0];
    const float* gamma = (const float*)d_in[1];
    const float* beta  = (const float*)d_in[2];
    const float* w_qkv = (const float*)d_in[3];
    const float* b_qkv = (const float*)d_in[4];
    const float* w_out = (const float*)d_in[5];
    const float* b_out = (const float*)d_in[6];
    float* y = (float*)d_out;

    __nv_bfloat16* wq; cudaGetSymbolAddress((void**)&wq, g_wqkvb);
    __nv_bfloat16* wo; cudaGetSymbolAddress((void**)&wo, g_woutb);

    const int SM_MIX = 3 * (ROWK_B + KROW_B);   // 107520
    const int SM_KK  = 6 * KROW_B;              // 104448
    const int SM_RR  = 6 * ROWK_B;              // 110592
    cudaFuncSetAttribute(qkv_kernel, cudaFuncAttributeMaxDynamicSharedMemorySize, SM_MIX);
    cudaFuncSetAttribute(s_kernel,   cudaFuncAttributeMaxDynamicSharedMemorySize, SM_KK);
    cudaFuncSetAttribute(av_kernel,  cudaFuncAttributeMaxDynamicSharedMemorySize, SM_RR);
    cudaFuncSetAttribute(out_kernel, cudaFuncAttributeMaxDynamicSharedMemorySize, SM_MIX);

    convert_kernel<<<768, 256>>>(w_qkv, wq, 3 * CH * CH / 4);
    convert_kernel<<<256, 256>>>(w_out, wo, CH * CH / 4);
    gn_kernel<<<BATCH * 32, 256>>>(x, gamma, beta);
    qkv_kernel<<<dim3(NSP / 128, 3 * CH / 128, BATCH), 256, SM_MIX>>>(b_qkv);
    s_kernel<<<dim3(NSP / 128, NSP / 128, BATCH), 256, SM_KK>>>();
    softmax_kernel<<<dim3(NSP, BATCH), 256>>>();
    av_kernel<<<dim3(CH / 128, NSP / 128, BATCH), 256, SM_RR>>>();
    out_kernel<<<dim3(NSP / 128, CH / 128, BATCH), 256, SM_MIX>>>(b_out, x, y);
}